// round 13
// baseline (speedup 1.0000x reference)
#include <cuda_runtime.h>
#include <cuda_fp16.h>
#include <cstdint>

// Problem constants
#define B_    2
#define S_    2048
#define E_    2048
#define H_    32
#define KH_   8
#define HD_   64
#define F_    8192
#define KV_   (KH_*HD_)      // 512
#define QKVN  (E_ + 2*KV_)   // 3072
#define M_    (B_*S_)        // 4096

#define GRID_P 304            // 2 CTAs x 152 SMs (GB300)

// -------- scratch (device globals: allocation-free) --------
__device__ __half g_wqkvh[(size_t)QKVN*E_];
__device__ __half g_woh  [(size_t)E_*E_];
__device__ __half g_w13h [(size_t)2*F_*E_];   // rows interleaved: 2j=w1_j, 2j+1=w3_j
__device__ __half g_w2h  [(size_t)E_*F_];

__device__ __half g_h    [(size_t)M_*E_];
__device__ __half g_qh   [(size_t)B_*H_ *S_*HD_];
__device__ __half g_kh   [(size_t)B_*KH_*S_*HD_];
__device__ __half g_vh   [(size_t)B_*KH_*S_*HD_];
__device__ __half g_o    [(size_t)M_*E_];
__device__ float  g_h2   [(size_t)M_*E_];
__device__ __half g_g    [(size_t)M_*E_];
__device__ __half g_act  [(size_t)M_*F_];

__device__ __forceinline__ uint32_t smem_u32(const void* p) {
    uint32_t a;
    asm("{ .reg .u64 t; cvta.to.shared.u64 t, %1; cvt.u32.u64 %0, t; }" : "=r"(a) : "l"(p));
    return a;
}
__device__ __forceinline__ uint32_t packh2(float a, float b) {
    __half2 h = __floats2half2_rn(a, b);
    return *reinterpret_cast<uint32_t*>(&h);
}
__device__ __forceinline__ float2 unpackh2(uint32_t u) {
    __half2 h = *reinterpret_cast<__half2*>(&u);
    return __half22float2(h);
}

// ============================================================
// fp32 -> fp16 bulk convert (plain). n % 1024 == 0.
// ============================================================
__global__ __launch_bounds__(256) void f2h_kernel(
    const float* __restrict__ in, __half* __restrict__ out)
{
    const size_t i = ((size_t)blockIdx.x * 256 + threadIdx.x) * 4;
    float4 v = *reinterpret_cast<const float4*>(in + i);
    uint2 o = make_uint2(packh2(v.x, v.y), packh2(v.z, v.w));
    *reinterpret_cast<uint2*>(out + i) = o;
}

// fp32 -> fp16 with row interleave: src row j -> dst row 2j+which (rowlen E_)
__global__ __launch_bounds__(256) void f2h_w13_kernel(
    const float* __restrict__ in, __half* __restrict__ out, int which)
{
    const size_t i = ((size_t)blockIdx.x * 256 + threadIdx.x) * 4;
    float4 v = *reinterpret_cast<const float4*>(in + i);
    const size_t row = i >> 11;            // / E_
    const size_t col = i & (E_ - 1);
    __half* dst = out + (((row << 1) + which) << 11) + col;
    uint2 o = make_uint2(packh2(v.x, v.y), packh2(v.z, v.w));
    *reinterpret_cast<uint2*>(dst) = o;
}

// ============================================================
// RMSNorm: fp32 in, fp16 out. one block per row of 2048
// ============================================================
__global__ __launch_bounds__(256) void rmsnorm_kernel(
    const float* __restrict__ x, const float* __restrict__ w, __half* __restrict__ o)
{
    const int tid = threadIdx.x;
    const size_t base = (size_t)blockIdx.x * E_;
    float4 v0 = *reinterpret_cast<const float4*>(x + base + tid*4);
    float4 v1 = *reinterpret_cast<const float4*>(x + base + 1024 + tid*4);
    float ss = v0.x*v0.x + v0.y*v0.y + v0.z*v0.z + v0.w*v0.w
             + v1.x*v1.x + v1.y*v1.y + v1.z*v1.z + v1.w*v1.w;
    #pragma unroll
    for (int off = 16; off; off >>= 1) ss += __shfl_xor_sync(0xffffffffu, ss, off);
    __shared__ float sred[8];
    if ((tid & 31) == 0) sred[tid >> 5] = ss;
    __syncthreads();
    float tot = 0.f;
    #pragma unroll
    for (int i = 0; i < 8; i++) tot += sred[i];
    float inv = rsqrtf(tot * (1.0f / (float)E_) + 1e-5f);
    float4 w0 = *reinterpret_cast<const float4*>(w + tid*4);
    float4 w1 = *reinterpret_cast<const float4*>(w + 1024 + tid*4);
    uint2 o0 = make_uint2(packh2(v0.x*inv*w0.x, v0.y*inv*w0.y),
                          packh2(v0.z*inv*w0.z, v0.w*inv*w0.w));
    uint2 o1 = make_uint2(packh2(v1.x*inv*w1.x, v1.y*inv*w1.y),
                          packh2(v1.z*inv*w1.z, v1.w*inv*w1.w));
    *reinterpret_cast<uint2*>(o + base + tid*4)        = o0;
    *reinterpret_cast<uint2*>(o + base + 1024 + tid*4) = o1;
}

// -------- fp16 mma --------
__device__ __forceinline__ void mma_f16(float* c,
    uint32_t a0, uint32_t a1, uint32_t a2, uint32_t a3,
    uint32_t b0, uint32_t b1)
{
    asm volatile(
        "mma.sync.aligned.m16n8k16.row.col.f32.f16.f16.f32 "
        "{%0,%1,%2,%3}, {%4,%5,%6,%7}, {%8,%9}, {%0,%1,%2,%3};"
        : "+f"(c[0]), "+f"(c[1]), "+f"(c[2]), "+f"(c[3])
        : "r"(a0), "r"(a1), "r"(a2), "r"(a3), "r"(b0), "r"(b1));
}

// interleave two uint4 (halves k0..7, k8..15) into perm slot order
__device__ __forceinline__ void perm_sts(__half* rowp, uint4 lo, uint4 hi) {
    *reinterpret_cast<uint4*>(rowp)     = make_uint4(lo.x, hi.x, lo.y, hi.y);
    *reinterpret_cast<uint4*>(rowp + 8) = make_uint4(lo.z, hi.z, lo.w, hi.w);
}

// RoPE rotate-and-scatter for one fp32 pair (c even), row in [0,M)
__device__ __forceinline__ void rope_store(float2 v, int row, int c,
    const float* __restrict__ fc,
    __half* __restrict__ qp, __half* __restrict__ kp, __half* __restrict__ vp)
{
    const int b = row >> 11, s = row & (S_ - 1);
    if (c < E_) {
        const int hh = c >> 6, d = c & 63;
        const float cs = fc[s*64 + d], sn = fc[s*64 + d + 1];
        *reinterpret_cast<uint32_t*>(qp + ((((size_t)b*H_ + hh)*S_ + s) << 6) + d) =
            packh2((v.x*cs - v.y*sn) * 0.125f, (v.y*cs + v.x*sn) * 0.125f);
    } else if (c < E_ + KV_) {
        const int kc = c - E_, kh = kc >> 6, d = kc & 63;
        const float cs = fc[s*64 + d], sn = fc[s*64 + d + 1];
        *reinterpret_cast<uint32_t*>(kp + ((((size_t)b*KH_ + kh)*S_ + s) << 6) + d) =
            packh2(v.x*cs - v.y*sn, v.y*cs + v.x*sn);
    } else {
        const int vc = c - E_ - KV_, kh = vc >> 6, d = vc & 63;
        *reinterpret_cast<uint32_t*>(vp + ((((size_t)b*KH_ + kh)*S_ + s) << 6) + d) =
            packh2(v.x, v.y);
    }
}

// ============================================================
// FP16-in tensor-core GEMM NT, PERSISTENT CTAs:
// grid = min(ntiles, GRID_P); each CTA loops tiles with stride gridDim.x.
// Block tile 128x128, K-tile 32, 256 thr (8 warps 4Mx2N), warp 32x64.
// MODE 0: C fp32 = A*B^T + Res
// MODE 1: rope epilogue -> q/k/v fp16 (qkv GEMM)
// MODE 2: swiglu epilogue -> act fp16 (w13 GEMM, interleaved rows)
// ============================================================
template<int MODE>
__global__ __launch_bounds__(256, 2) void hgemm16(
    const __half* __restrict__ A, const __half* __restrict__ B,
    const float* __restrict__ Res, void* __restrict__ Cv,
    const float* __restrict__ fcp,
    __half* __restrict__ qp, __half* __restrict__ kp, __half* __restrict__ vp,
    int M, int N, int K)
{
    __shared__ __align__(16) __half As[2][2][128][16];
    __shared__ __align__(16) __half Bs[2][2][128][16];

    const int tid  = threadIdx.x;
    const int lane = tid & 31;
    const int warp = tid >> 5;

    const int m0 = (warp & 3) * 32;
    const int n0 = (warp >> 2) * 64;

    const int r_l  = tid >> 1;    // 0..127
    const int kk_l = tid & 1;     // 0..1
    const int gr = lane >> 2;
    const int tq = lane & 3;
    const int KT = K >> 5;

    const int nbn = N >> 7;
    const int ntiles = (M >> 7) * nbn;

    for (int t = blockIdx.x; t < ntiles; t += gridDim.x) {
        const int bm = (t / nbn) << 7;
        const int bn = (t % nbn) << 7;
        const __half* Ag = A + (size_t)(bm + r_l) * K + kk_l * 16;
        const __half* Bg = B + (size_t)(bn + r_l) * K + kk_l * 16;

        float acc[2][8][4];
        #pragma unroll
        for (int i = 0; i < 2; i++)
            #pragma unroll
            for (int j = 0; j < 8; j++)
                acc[i][j][0] = acc[i][j][1] = acc[i][j][2] = acc[i][j][3] = 0.f;

        __syncthreads();   // previous tile's smem reads complete
        {
            uint4 a0 = *reinterpret_cast<const uint4*>(Ag);
            uint4 a1 = *reinterpret_cast<const uint4*>(Ag + 8);
            uint4 b0 = *reinterpret_cast<const uint4*>(Bg);
            uint4 b1 = *reinterpret_cast<const uint4*>(Bg + 8);
            perm_sts(&As[0][kk_l][r_l][0], a0, a1);
            perm_sts(&Bs[0][kk_l][r_l][0], b0, b1);
        }
        __syncthreads();

        for (int kt = 0; kt < KT; ++kt) {
            const int buf = kt & 1;
            const bool pf = (kt + 1 < KT);
            uint4 pa0, pa1, pb0, pb1;
            if (pf) {
                const __half* Ap = Ag + (size_t)(kt + 1) * 32;
                const __half* Bp = Bg + (size_t)(kt + 1) * 32;
                pa0 = *reinterpret_cast<const uint4*>(Ap);
                pa1 = *reinterpret_cast<const uint4*>(Ap + 8);
                pb0 = *reinterpret_cast<const uint4*>(Bp);
                pb1 = *reinterpret_cast<const uint4*>(Bp + 8);
            }

            #pragma unroll
            for (int kk = 0; kk < 2; ++kk) {
                uint2 ax[2], ay[2];
                #pragma unroll
                for (int mi = 0; mi < 2; mi++) {
                    const int r = m0 + mi * 16 + gr;
                    ax[mi] = *reinterpret_cast<const uint2*>(&As[buf][kk][r    ][tq * 4]);
                    ay[mi] = *reinterpret_cast<const uint2*>(&As[buf][kk][r + 8][tq * 4]);
                }
                #pragma unroll
                for (int ni = 0; ni < 8; ni++) {
                    const uint2 bv = *reinterpret_cast<const uint2*>(&Bs[buf][kk][n0 + ni * 8 + gr][tq * 4]);
                    #pragma unroll
                    for (int mi = 0; mi < 2; mi++)
                        mma_f16(acc[mi][ni], ax[mi].x, ay[mi].x, ax[mi].y, ay[mi].y, bv.x, bv.y);
                }
            }

            if (pf) {
                const int nxt = buf ^ 1;
                perm_sts(&As[nxt][kk_l][r_l][0], pa0, pa1);
                perm_sts(&Bs[nxt][kk_l][r_l][0], pb0, pb1);
                __syncthreads();
            }
        }

        // ---- epilogue ----
        const int gc = tq * 2;
        #pragma unroll
        for (int mi = 0; mi < 2; mi++) {
            #pragma unroll
            for (int ni = 0; ni < 8; ni++) {
                const int r = bm + m0 + mi * 16 + gr;
                const int c = bn + n0 + ni * 8 + gc;
                float2 lo = make_float2(acc[mi][ni][0], acc[mi][ni][1]);
                float2 hi = make_float2(acc[mi][ni][2], acc[mi][ni][3]);
                if (MODE == 0) {
                    float2 rlo = *reinterpret_cast<const float2*>(Res + (size_t)r * N + c);
                    float2 rhi = *reinterpret_cast<const float2*>(Res + (size_t)(r + 8) * N + c);
                    lo.x += rlo.x; lo.y += rlo.y;
                    hi.x += rhi.x; hi.y += rhi.y;
                    float* C = (float*)Cv;
                    *reinterpret_cast<float2*>(C + (size_t)r * N + c)       = lo;
                    *reinterpret_cast<float2*>(C + (size_t)(r + 8) * N + c) = hi;
                } else if (MODE == 1) {
                    rope_store(lo, r,     c, fcp, qp, kp, vp);
                    rope_store(hi, r + 8, c, fcp, qp, kp, vp);
                } else {
                    const int j = c >> 1;
                    const float a0 = lo.x * lo.y / (1.f + __expf(-lo.x));
                    const float a1 = hi.x * hi.y / (1.f + __expf(-hi.x));
                    __half* act = (__half*)Cv;
                    act[(size_t)r * F_ + j]       = __float2half(a0);
                    act[(size_t)(r + 8) * F_ + j] = __float2half(a1);
                }
            }
        }
    }
}

// ============================================================
// Flash attention, fp16 mma, causal, GQA 4:1. fp16 output (plain).
// 128 q-rows x 64 k-cols per block, 256 thr (8 warps x 16 rows).
// ============================================================
__global__ __launch_bounds__(256) void attn_mma_kernel(
    const __half* __restrict__ qr, const __half* __restrict__ kr,
    const __half* __restrict__ vr, __half* __restrict__ of)
{
    __shared__ __align__(16) __half sQ[4][128][16];
    __shared__ __align__(16) __half sK[4][64][16];
    __shared__ __align__(16) __half sV[64][72];

    const int tid  = threadIdx.x;
    const int lane = tid & 31, warp = tid >> 5;
    const int qt = blockIdx.x, h = blockIdx.y, b = blockIdx.z;
    const int kvh = h >> 2;
    const __half* Q = qr + (((size_t)(b*H_ + h)) * S_ + qt*128) * HD_;
    const __half* K = kr + ((size_t)(b*KH_ + kvh)) * S_ * HD_;
    const __half* V = vr + ((size_t)(b*KH_ + kvh)) * S_ * HD_;

    #pragma unroll
    for (int it = 0; it < 4; it++) {
        const int f = tid + it*256;
        const int r = f >> 3, seg = f & 7;
        const int g = seg >> 1, hp = seg & 1;
        uint4 v4 = *reinterpret_cast<const uint4*>(Q + (size_t)r*64 + seg*8);
        uint32_t* p = reinterpret_cast<uint32_t*>(&sQ[g][r][0]);
        p[hp] = v4.x; p[hp+2] = v4.y; p[hp+4] = v4.z; p[hp+6] = v4.w;
    }

    const int gr = lane >> 2;
    const int tq = lane & 3;
    const int qrow = warp * 16;
    const int lm_r = (lane & 7) + ((lane >> 3) & 1) * 8;
    const int lm_c = ((lane >> 4) & 1) * 8;

    float m0 = -1e30f, m1 = -1e30f, l0 = 0.f, l1 = 0.f;
    float oac[8][4];
    #pragma unroll
    for (int i = 0; i < 8; i++)
        oac[i][0] = oac[i][1] = oac[i][2] = oac[i][3] = 0.f;

    const int KTILES = 2*qt + 2;
    for (int kt = 0; kt < KTILES; ++kt) {
        __syncthreads();
        #pragma unroll
        for (int it = 0; it < 2; it++) {
            const int f = tid + it*256;
            const int r = f >> 3, seg = f & 7;
            const int g = seg >> 1, hp = seg & 1;
            uint4 kv4 = *reinterpret_cast<const uint4*>(K + ((size_t)kt*64 + r)*64 + seg*8);
            uint32_t* p = reinterpret_cast<uint32_t*>(&sK[g][r][0]);
            p[hp] = kv4.x; p[hp+2] = kv4.y; p[hp+4] = kv4.z; p[hp+6] = kv4.w;
            uint4 vv4 = *reinterpret_cast<const uint4*>(V + ((size_t)kt*64 + r)*64 + seg*8);
            *reinterpret_cast<uint4*>(&sV[r][seg*8]) = vv4;
        }
        __syncthreads();

        float sc[8][4];
        #pragma unroll
        for (int i = 0; i < 8; i++)
            sc[i][0] = sc[i][1] = sc[i][2] = sc[i][3] = 0.f;
        #pragma unroll
        for (int kk = 0; kk < 4; kk++) {
            const uint2 alo = *reinterpret_cast<const uint2*>(&sQ[kk][qrow + gr    ][tq*4]);
            const uint2 ahi = *reinterpret_cast<const uint2*>(&sQ[kk][qrow + gr + 8][tq*4]);
            #pragma unroll
            for (int ni = 0; ni < 8; ni++) {
                const uint2 bv = *reinterpret_cast<const uint2*>(&sK[kk][ni*8 + gr][tq*4]);
                mma_f16(sc[ni], alo.x, ahi.x, alo.y, ahi.y, bv.x, bv.y);
            }
        }

        if (kt >= 2*qt) {
            const int r0g = qt*128 + qrow + gr;
            const int r1g = r0g + 8;
            #pragma unroll
            for (int ni = 0; ni < 8; ni++) {
                const int c0 = kt*64 + ni*8 + tq*2, c1 = c0 + 1;
                if (c0 > r0g) sc[ni][0] = -1e30f;
                if (c1 > r0g) sc[ni][1] = -1e30f;
                if (c0 > r1g) sc[ni][2] = -1e30f;
                if (c1 > r1g) sc[ni][3] = -1e30f;
            }
        }

        float mx0 = -1e30f, mx1 = -1e30f;
        #pragma unroll
        for (int ni = 0; ni < 8; ni++) {
            mx0 = fmaxf(mx0, fmaxf(sc[ni][0], sc[ni][1]));
            mx1 = fmaxf(mx1, fmaxf(sc[ni][2], sc[ni][3]));
        }
        mx0 = fmaxf(mx0, __shfl_xor_sync(0xffffffffu, mx0, 1));
        mx0 = fmaxf(mx0, __shfl_xor_sync(0xffffffffu, mx0, 2));
        mx1 = fmaxf(mx1, __shfl_xor_sync(0xffffffffu, mx1, 1));
        mx1 = fmaxf(mx1, __shfl_xor_sync(0xffffffffu, mx1, 2));
        const float nm0 = fmaxf(m0, mx0), nm1 = fmaxf(m1, mx1);
        const float al0 = __expf(m0 - nm0), al1 = __expf(m1 - nm1);
        m0 = nm0; m1 = nm1;

        float s0 = 0.f, s1 = 0.f;
        uint32_t pa[4][4];
        #pragma unroll
        for (int ni = 0; ni < 8; ni++) {
            const float p0 = __expf(sc[ni][0] - nm0);
            const float p1 = __expf(sc[ni][1] - nm0);
            const float p2 = __expf(sc[ni][2] - nm1);
            const float p3 = __expf(sc[ni][3] - nm1);
            s0 += p0 + p1; s1 += p2 + p3;
            const int kk = ni >> 1, w2 = (ni & 1) * 2;
            pa[kk][w2    ] = packh2(p0, p1);
            pa[kk][w2 + 1] = packh2(p2, p3);
        }
        s0 += __shfl_xor_sync(0xffffffffu, s0, 1);
        s0 += __shfl_xor_sync(0xffffffffu, s0, 2);
        s1 += __shfl_xor_sync(0xffffffffu, s1, 1);
        s1 += __shfl_xor_sync(0xffffffffu, s1, 2);
        l0 = l0 * al0 + s0;
        l1 = l1 * al1 + s1;
        #pragma unroll
        for (int ni = 0; ni < 8; ni++) {
            oac[ni][0] *= al0; oac[ni][1] *= al0;
            oac[ni][2] *= al1; oac[ni][3] *= al1;
        }

        #pragma unroll
        for (int kk = 0; kk < 4; kk++) {
            uint32_t bfr[8][2];
            #pragma unroll
            for (int nip = 0; nip < 4; nip++) {
                const uint32_t addr = smem_u32(&sV[16*kk + lm_r][nip*16 + lm_c]);
                asm volatile(
                    "ldmatrix.sync.aligned.m8n8.x4.trans.shared.b16 {%0,%1,%2,%3}, [%4];"
                    : "=r"(bfr[2*nip][0]), "=r"(bfr[2*nip][1]),
                      "=r"(bfr[2*nip+1][0]), "=r"(bfr[2*nip+1][1])
                    : "r"(addr));
            }
            #pragma unroll
            for (int ni = 0; ni < 8; ni++)
                mma_f16(oac[ni], pa[kk][0], pa[kk][1], pa[kk][2], pa[kk][3],
                        bfr[ni][0], bfr[ni][1]);
        }
    }

    const float il0 = 1.0f / l0, il1 = 1.0f / l1;
    const size_t row0 = (size_t)b * S_ + qt*128 + qrow + gr;
    __half* o0 = of + row0 * E_ + h*64;
    __half* o1 = o0 + (size_t)8 * E_;
    #pragma unroll
    for (int ni = 0; ni < 8; ni++) {
        *reinterpret_cast<uint32_t*>(o0 + ni*8 + tq*2) = packh2(oac[ni][0]*il0, oac[ni][1]*il0);
        *reinterpret_cast<uint32_t*>(o1 + ni*8 + tq*2) = packh2(oac[ni][2]*il1, oac[ni][3]*il1);
    }
}

static inline int pgrid(int M, int N) {
    const int nt = (M >> 7) * (N >> 7);
    return nt < GRID_P ? nt : GRID_P;
}

// ============================================================
// launch — side stream converts all weights concurrently with the
// main compute chain; join points placed at first use.
// ============================================================
extern "C" void kernel_launch(void* const* d_in, const int* in_sizes, int n_in,
                              void* d_out, int out_size)
{
    (void)in_sizes; (void)n_in; (void)out_size;
    const float* x     = (const float*)d_in[0];
    const float* fc    = (const float*)d_in[2];
    const float* w_qkv = (const float*)d_in[3];
    const float* w_o   = (const float*)d_in[4];
    const float* w1    = (const float*)d_in[5];
    const float* w2    = (const float*)d_in[6];
    const float* w3    = (const float*)d_in[7];
    const float* anw   = (const float*)d_in[8];
    const float* fnw   = (const float*)d_in[9];
    float* out = (float*)d_out;

    __half *wqkvh, *woh, *w13h, *w2h;
    __half *h, *qh, *kh, *vh, *o, *g, *act;
    float  *h2;
    cudaGetSymbolAddress((void**)&wqkvh, g_wqkvh);
    cudaGetSymbolAddress((void**)&woh,   g_woh);
    cudaGetSymbolAddress((void**)&w13h,  g_w13h);
    cudaGetSymbolAddress((void**)&w2h,   g_w2h);
    cudaGetSymbolAddress((void**)&h,     g_h);
    cudaGetSymbolAddress((void**)&qh,    g_qh);
    cudaGetSymbolAddress((void**)&kh,    g_kh);
    cudaGetSymbolAddress((void**)&vh,    g_vh);
    cudaGetSymbolAddress((void**)&o,     g_o);
    cudaGetSymbolAddress((void**)&h2,    g_h2);
    cudaGetSymbolAddress((void**)&g,     g_g);
    cudaGetSymbolAddress((void**)&act,   g_act);

    // Side stream + fork/join events (host objects; created per call, bounded leak).
    cudaStream_t s2;
    cudaEvent_t evFork, evQkvW, evJoin;
    cudaStreamCreateWithFlags(&s2, cudaStreamNonBlocking);
    cudaEventCreateWithFlags(&evFork, cudaEventDisableTiming);
    cudaEventCreateWithFlags(&evQkvW, cudaEventDisableTiming);
    cudaEventCreateWithFlags(&evJoin, cudaEventDisableTiming);

    // fork
    cudaEventRecord(evFork, 0);
    cudaStreamWaitEvent(s2, evFork, 0);

    // side stream: qkv weights first (needed soonest), then the rest
    f2h_kernel<<<(QKVN*E_)/1024, 256, 0, s2>>>(w_qkv, wqkvh);
    cudaEventRecord(evQkvW, s2);
    f2h_kernel<<<(E_*E_)/1024, 256, 0, s2>>>(w_o, woh);
    f2h_w13_kernel<<<(F_*E_)/1024, 256, 0, s2>>>(w1, w13h, 0);
    f2h_w13_kernel<<<(F_*E_)/1024, 256, 0, s2>>>(w3, w13h, 1);
    f2h_kernel<<<(E_*F_)/1024, 256, 0, s2>>>(w2, w2h);
    cudaEventRecord(evJoin, s2);

    // main stream: rmsnorm overlaps qkv weight conversion
    rmsnorm_kernel<<<M_, 256>>>(x, anw, h);
    cudaStreamWaitEvent(0, evQkvW, 0);
    hgemm16<1><<<pgrid(M_, QKVN), 256>>>(h, wqkvh, nullptr, nullptr,
                                         fc, qh, kh, vh, M_, QKVN, E_);
    attn_mma_kernel<<<dim3(S_/128, H_, B_), 256>>>(qh, kh, vh, o);

    // join: remaining GEMMs need the side-stream weights
    cudaStreamWaitEvent(0, evJoin, 0);

    // h2 = x + o @ w_o^T
    hgemm16<0><<<pgrid(M_, E_), 256>>>(o, woh, x, h2,
                                       nullptr, nullptr, nullptr, nullptr, M_, E_, E_);
    // ffn rmsnorm
    rmsnorm_kernel<<<M_, 256>>>(h2, fnw, g);
    // w13 GEMM + fused SwiGLU
    hgemm16<2><<<pgrid(M_, 2*F_), 256>>>(g, w13h, nullptr, act,
                                         nullptr, nullptr, nullptr, nullptr, M_, 2*F_, E_);
    // out = h2 + act @ w2^T
    hgemm16<0><<<pgrid(M_, E_), 256>>>(act, w2h, h2, out,
                                       nullptr, nullptr, nullptr, nullptr, M_, E_, F_);
}

// round 14
// speedup vs baseline: 1.0115x; 1.0115x over previous
#include <cuda_runtime.h>
#include <cuda_fp16.h>
#include <cstdint>

// Problem constants
#define B_    2
#define S_    2048
#define E_    2048
#define H_    32
#define KH_   8
#define HD_   64
#define F_    8192
#define KV_   (KH_*HD_)      // 512
#define QKVN  (E_ + 2*KV_)   // 3072
#define M_    (B_*S_)        // 4096

// -------- scratch (device globals: allocation-free) --------
__device__ __half g_wqkvh[(size_t)QKVN*E_];
__device__ __half g_woh  [(size_t)E_*E_];
__device__ __half g_w13h [(size_t)2*F_*E_];   // rows interleaved: 2j=w1_j, 2j+1=w3_j
__device__ __half g_w2h  [(size_t)E_*F_];

__device__ __half g_h    [(size_t)M_*E_];
__device__ __half g_qh   [(size_t)B_*H_ *S_*HD_];
__device__ __half g_kh   [(size_t)B_*KH_*S_*HD_];
__device__ __half g_vh   [(size_t)B_*KH_*S_*HD_];
__device__ __half g_o    [(size_t)M_*E_];
__device__ float  g_h2   [(size_t)M_*E_];
__device__ __half g_g    [(size_t)M_*E_];
__device__ __half g_act  [(size_t)M_*F_];

__device__ __forceinline__ uint32_t smem_u32(const void* p) {
    uint32_t a;
    asm("{ .reg .u64 t; cvta.to.shared.u64 t, %1; cvt.u32.u64 %0, t; }" : "=r"(a) : "l"(p));
    return a;
}
__device__ __forceinline__ uint32_t packh2(float a, float b) {
    __half2 h = __floats2half2_rn(a, b);
    return *reinterpret_cast<uint32_t*>(&h);
}
__device__ __forceinline__ float2 unpackh2(uint32_t u) {
    __half2 h = *reinterpret_cast<__half2*>(&u);
    return __half22float2(h);
}

// ============================================================
// fp32 -> fp16 bulk convert; 8 elems/thread, 2 independent LDG.128,
// single STG.128. n % 2048 == 0.
// ============================================================
__global__ __launch_bounds__(256) void f2h_kernel(
    const float* __restrict__ in, __half* __restrict__ out)
{
    const size_t i = ((size_t)blockIdx.x * 256 + threadIdx.x) * 8;
    float4 v0 = *reinterpret_cast<const float4*>(in + i);
    float4 v1 = *reinterpret_cast<const float4*>(in + i + 4);
    uint4 o = make_uint4(packh2(v0.x, v0.y), packh2(v0.z, v0.w),
                         packh2(v1.x, v1.y), packh2(v1.z, v1.w));
    *reinterpret_cast<uint4*>(out + i) = o;
}

// fp32 -> fp16 with row interleave: src row j -> dst row 2j+which (rowlen E_)
// 8 elems/thread (E_ % 8 == 0 so all 8 stay in one row).
__global__ __launch_bounds__(256) void f2h_w13_kernel(
    const float* __restrict__ in, __half* __restrict__ out, int which)
{
    const size_t i = ((size_t)blockIdx.x * 256 + threadIdx.x) * 8;
    float4 v0 = *reinterpret_cast<const float4*>(in + i);
    float4 v1 = *reinterpret_cast<const float4*>(in + i + 4);
    const size_t row = i >> 11;            // / E_
    const size_t col = i & (E_ - 1);
    __half* dst = out + (((row << 1) + which) << 11) + col;
    uint4 o = make_uint4(packh2(v0.x, v0.y), packh2(v0.z, v0.w),
                         packh2(v1.x, v1.y), packh2(v1.z, v1.w));
    *reinterpret_cast<uint4*>(dst) = o;
}

// ============================================================
// RMSNorm: fp32 in, fp16 out. one block per row of 2048
// ============================================================
__global__ __launch_bounds__(256) void rmsnorm_kernel(
    const float* __restrict__ x, const float* __restrict__ w, __half* __restrict__ o)
{
    const int tid = threadIdx.x;
    const size_t base = (size_t)blockIdx.x * E_;
    float4 v0 = *reinterpret_cast<const float4*>(x + base + tid*4);
    float4 v1 = *reinterpret_cast<const float4*>(x + base + 1024 + tid*4);
    float ss = v0.x*v0.x + v0.y*v0.y + v0.z*v0.z + v0.w*v0.w
             + v1.x*v1.x + v1.y*v1.y + v1.z*v1.z + v1.w*v1.w;
    #pragma unroll
    for (int off = 16; off; off >>= 1) ss += __shfl_xor_sync(0xffffffffu, ss, off);
    __shared__ float sred[8];
    if ((tid & 31) == 0) sred[tid >> 5] = ss;
    __syncthreads();
    float tot = 0.f;
    #pragma unroll
    for (int i = 0; i < 8; i++) tot += sred[i];
    float inv = rsqrtf(tot * (1.0f / (float)E_) + 1e-5f);
    float4 w0 = *reinterpret_cast<const float4*>(w + tid*4);
    float4 w1 = *reinterpret_cast<const float4*>(w + 1024 + tid*4);
    uint2 o0 = make_uint2(packh2(v0.x*inv*w0.x, v0.y*inv*w0.y),
                          packh2(v0.z*inv*w0.z, v0.w*inv*w0.w));
    uint2 o1 = make_uint2(packh2(v1.x*inv*w1.x, v1.y*inv*w1.y),
                          packh2(v1.z*inv*w1.z, v1.w*inv*w1.w));
    *reinterpret_cast<uint2*>(o + base + tid*4)        = o0;
    *reinterpret_cast<uint2*>(o + base + 1024 + tid*4) = o1;
}

// -------- fp16 mma --------
__device__ __forceinline__ void mma_f16(float* c,
    uint32_t a0, uint32_t a1, uint32_t a2, uint32_t a3,
    uint32_t b0, uint32_t b1)
{
    asm volatile(
        "mma.sync.aligned.m16n8k16.row.col.f32.f16.f16.f32 "
        "{%0,%1,%2,%3}, {%4,%5,%6,%7}, {%8,%9}, {%0,%1,%2,%3};"
        : "+f"(c[0]), "+f"(c[1]), "+f"(c[2]), "+f"(c[3])
        : "r"(a0), "r"(a1), "r"(a2), "r"(a3), "r"(b0), "r"(b1));
}

// interleave two uint4 (halves k0..7, k8..15) into perm slot order
__device__ __forceinline__ void perm_sts(__half* rowp, uint4 lo, uint4 hi) {
    *reinterpret_cast<uint4*>(rowp)     = make_uint4(lo.x, hi.x, lo.y, hi.y);
    *reinterpret_cast<uint4*>(rowp + 8) = make_uint4(lo.z, hi.z, lo.w, hi.w);
}

// RoPE rotate-and-scatter for one fp32 pair (c even), row in [0,M)
__device__ __forceinline__ void rope_store(float2 v, int row, int c,
    const float* __restrict__ fc,
    __half* __restrict__ qp, __half* __restrict__ kp, __half* __restrict__ vp)
{
    const int b = row >> 11, s = row & (S_ - 1);
    if (c < E_) {
        const int hh = c >> 6, d = c & 63;
        const float cs = fc[s*64 + d], sn = fc[s*64 + d + 1];
        *reinterpret_cast<uint32_t*>(qp + ((((size_t)b*H_ + hh)*S_ + s) << 6) + d) =
            packh2((v.x*cs - v.y*sn) * 0.125f, (v.y*cs + v.x*sn) * 0.125f);
    } else if (c < E_ + KV_) {
        const int kc = c - E_, kh = kc >> 6, d = kc & 63;
        const float cs = fc[s*64 + d], sn = fc[s*64 + d + 1];
        *reinterpret_cast<uint32_t*>(kp + ((((size_t)b*KH_ + kh)*S_ + s) << 6) + d) =
            packh2(v.x*cs - v.y*sn, v.y*cs + v.x*sn);
    } else {
        const int vc = c - E_ - KV_, kh = vc >> 6, d = vc & 63;
        *reinterpret_cast<uint32_t*>(vp + ((((size_t)b*KH_ + kh)*S_ + s) << 6) + d) =
            packh2(v.x, v.y);
    }
}

// ============================================================
// FP16-in tensor-core GEMM NT (proven R12 form):
// Block 128x128, K-tile 32, 256 thr (8 warps 4Mx2N), warp 32x64.
// MODE 0: C fp32 = A*B^T + Res
// MODE 1: rope epilogue -> q/k/v fp16 (qkv GEMM)
// MODE 2: swiglu epilogue -> act fp16 (w13 GEMM, interleaved rows)
// ============================================================
template<int MODE>
__global__ __launch_bounds__(256, 2) void hgemm16(
    const __half* __restrict__ A, const __half* __restrict__ B,
    const float* __restrict__ Res, void* __restrict__ Cv,
    const float* __restrict__ fcp,
    __half* __restrict__ qp, __half* __restrict__ kp, __half* __restrict__ vp,
    int M, int N, int K)
{
    __shared__ __align__(16) __half As[2][2][128][16];
    __shared__ __align__(16) __half Bs[2][2][128][16];

    const int tid  = threadIdx.x;
    const int lane = tid & 31;
    const int warp = tid >> 5;
    const int bm = blockIdx.y * 128;
    const int bn = blockIdx.x * 128;

    const int m0 = (warp & 3) * 32;
    const int n0 = (warp >> 2) * 64;

    const int r_l  = tid >> 1;    // 0..127
    const int kk_l = tid & 1;     // 0..1
    const __half* Ag = A + (size_t)(bm + r_l) * K + kk_l * 16;
    const __half* Bg = B + (size_t)(bn + r_l) * K + kk_l * 16;

    float acc[2][8][4];
    #pragma unroll
    for (int i = 0; i < 2; i++)
        #pragma unroll
        for (int j = 0; j < 8; j++)
            acc[i][j][0] = acc[i][j][1] = acc[i][j][2] = acc[i][j][3] = 0.f;

    {
        uint4 a0 = *reinterpret_cast<const uint4*>(Ag);
        uint4 a1 = *reinterpret_cast<const uint4*>(Ag + 8);
        uint4 b0 = *reinterpret_cast<const uint4*>(Bg);
        uint4 b1 = *reinterpret_cast<const uint4*>(Bg + 8);
        perm_sts(&As[0][kk_l][r_l][0], a0, a1);
        perm_sts(&Bs[0][kk_l][r_l][0], b0, b1);
    }
    __syncthreads();

    const int gr = lane >> 2;
    const int tq = lane & 3;
    const int KT = K >> 5;

    for (int kt = 0; kt < KT; ++kt) {
        const int buf = kt & 1;
        const bool pf = (kt + 1 < KT);
        uint4 pa0, pa1, pb0, pb1;
        if (pf) {
            const __half* Ap = Ag + (size_t)(kt + 1) * 32;
            const __half* Bp = Bg + (size_t)(kt + 1) * 32;
            pa0 = *reinterpret_cast<const uint4*>(Ap);
            pa1 = *reinterpret_cast<const uint4*>(Ap + 8);
            pb0 = *reinterpret_cast<const uint4*>(Bp);
            pb1 = *reinterpret_cast<const uint4*>(Bp + 8);
        }

        #pragma unroll
        for (int kk = 0; kk < 2; ++kk) {
            uint2 ax[2], ay[2];
            #pragma unroll
            for (int mi = 0; mi < 2; mi++) {
                const int r = m0 + mi * 16 + gr;
                ax[mi] = *reinterpret_cast<const uint2*>(&As[buf][kk][r    ][tq * 4]);
                ay[mi] = *reinterpret_cast<const uint2*>(&As[buf][kk][r + 8][tq * 4]);
            }
            #pragma unroll
            for (int ni = 0; ni < 8; ni++) {
                const uint2 bv = *reinterpret_cast<const uint2*>(&Bs[buf][kk][n0 + ni * 8 + gr][tq * 4]);
                #pragma unroll
                for (int mi = 0; mi < 2; mi++)
                    mma_f16(acc[mi][ni], ax[mi].x, ay[mi].x, ax[mi].y, ay[mi].y, bv.x, bv.y);
            }
        }

        if (pf) {
            const int nxt = buf ^ 1;
            perm_sts(&As[nxt][kk_l][r_l][0], pa0, pa1);
            perm_sts(&Bs[nxt][kk_l][r_l][0], pb0, pb1);
            __syncthreads();
        }
    }

    // ---- epilogue ----
    const int gc = tq * 2;
    #pragma unroll
    for (int mi = 0; mi < 2; mi++) {
        #pragma unroll
        for (int ni = 0; ni < 8; ni++) {
            const int r = bm + m0 + mi * 16 + gr;
            const int c = bn + n0 + ni * 8 + gc;
            float2 lo = make_float2(acc[mi][ni][0], acc[mi][ni][1]);
            float2 hi = make_float2(acc[mi][ni][2], acc[mi][ni][3]);
            if (MODE == 0) {
                float2 rlo = *reinterpret_cast<const float2*>(Res + (size_t)r * N + c);
                float2 rhi = *reinterpret_cast<const float2*>(Res + (size_t)(r + 8) * N + c);
                lo.x += rlo.x; lo.y += rlo.y;
                hi.x += rhi.x; hi.y += rhi.y;
                float* C = (float*)Cv;
                *reinterpret_cast<float2*>(C + (size_t)r * N + c)       = lo;
                *reinterpret_cast<float2*>(C + (size_t)(r + 8) * N + c) = hi;
            } else if (MODE == 1) {
                rope_store(lo, r,     c, fcp, qp, kp, vp);
                rope_store(hi, r + 8, c, fcp, qp, kp, vp);
            } else {
                const int j = c >> 1;
                const float a0 = lo.x * lo.y / (1.f + __expf(-lo.x));
                const float a1 = hi.x * hi.y / (1.f + __expf(-hi.x));
                __half* act = (__half*)Cv;
                act[(size_t)r * F_ + j]       = __float2half(a0);
                act[(size_t)(r + 8) * F_ + j] = __float2half(a1);
            }
        }
    }
}

// ============================================================
// Flash attention, fp16 mma, causal, GQA 4:1. fp16 output (plain).
// 128 q-rows x 64 k-cols per block, 256 thr (8 warps x 16 rows).
// ============================================================
__global__ __launch_bounds__(256) void attn_mma_kernel(
    const __half* __restrict__ qr, const __half* __restrict__ kr,
    const __half* __restrict__ vr, __half* __restrict__ of)
{
    __shared__ __align__(16) __half sQ[4][128][16];
    __shared__ __align__(16) __half sK[4][64][16];
    __shared__ __align__(16) __half sV[64][72];

    const int tid  = threadIdx.x;
    const int lane = tid & 31, warp = tid >> 5;
    const int qt = blockIdx.x, h = blockIdx.y, b = blockIdx.z;
    const int kvh = h >> 2;
    const __half* Q = qr + (((size_t)(b*H_ + h)) * S_ + qt*128) * HD_;
    const __half* K = kr + ((size_t)(b*KH_ + kvh)) * S_ * HD_;
    const __half* V = vr + ((size_t)(b*KH_ + kvh)) * S_ * HD_;

    #pragma unroll
    for (int it = 0; it < 4; it++) {
        const int f = tid + it*256;
        const int r = f >> 3, seg = f & 7;
        const int g = seg >> 1, hp = seg & 1;
        uint4 v4 = *reinterpret_cast<const uint4*>(Q + (size_t)r*64 + seg*8);
        uint32_t* p = reinterpret_cast<uint32_t*>(&sQ[g][r][0]);
        p[hp] = v4.x; p[hp+2] = v4.y; p[hp+4] = v4.z; p[hp+6] = v4.w;
    }

    const int gr = lane >> 2;
    const int tq = lane & 3;
    const int qrow = warp * 16;
    const int lm_r = (lane & 7) + ((lane >> 3) & 1) * 8;
    const int lm_c = ((lane >> 4) & 1) * 8;

    float m0 = -1e30f, m1 = -1e30f, l0 = 0.f, l1 = 0.f;
    float oac[8][4];
    #pragma unroll
    for (int i = 0; i < 8; i++)
        oac[i][0] = oac[i][1] = oac[i][2] = oac[i][3] = 0.f;

    const int KTILES = 2*qt + 2;
    for (int kt = 0; kt < KTILES; ++kt) {
        __syncthreads();
        #pragma unroll
        for (int it = 0; it < 2; it++) {
            const int f = tid + it*256;
            const int r = f >> 3, seg = f & 7;
            const int g = seg >> 1, hp = seg & 1;
            uint4 kv4 = *reinterpret_cast<const uint4*>(K + ((size_t)kt*64 + r)*64 + seg*8);
            uint32_t* p = reinterpret_cast<uint32_t*>(&sK[g][r][0]);
            p[hp] = kv4.x; p[hp+2] = kv4.y; p[hp+4] = kv4.z; p[hp+6] = kv4.w;
            uint4 vv4 = *reinterpret_cast<const uint4*>(V + ((size_t)kt*64 + r)*64 + seg*8);
            *reinterpret_cast<uint4*>(&sV[r][seg*8]) = vv4;
        }
        __syncthreads();

        float sc[8][4];
        #pragma unroll
        for (int i = 0; i < 8; i++)
            sc[i][0] = sc[i][1] = sc[i][2] = sc[i][3] = 0.f;
        #pragma unroll
        for (int kk = 0; kk < 4; kk++) {
            const uint2 alo = *reinterpret_cast<const uint2*>(&sQ[kk][qrow + gr    ][tq*4]);
            const uint2 ahi = *reinterpret_cast<const uint2*>(&sQ[kk][qrow + gr + 8][tq*4]);
            #pragma unroll
            for (int ni = 0; ni < 8; ni++) {
                const uint2 bv = *reinterpret_cast<const uint2*>(&sK[kk][ni*8 + gr][tq*4]);
                mma_f16(sc[ni], alo.x, ahi.x, alo.y, ahi.y, bv.x, bv.y);
            }
        }

        if (kt >= 2*qt) {
            const int r0g = qt*128 + qrow + gr;
            const int r1g = r0g + 8;
            #pragma unroll
            for (int ni = 0; ni < 8; ni++) {
                const int c0 = kt*64 + ni*8 + tq*2, c1 = c0 + 1;
                if (c0 > r0g) sc[ni][0] = -1e30f;
                if (c1 > r0g) sc[ni][1] = -1e30f;
                if (c0 > r1g) sc[ni][2] = -1e30f;
                if (c1 > r1g) sc[ni][3] = -1e30f;
            }
        }

        float mx0 = -1e30f, mx1 = -1e30f;
        #pragma unroll
        for (int ni = 0; ni < 8; ni++) {
            mx0 = fmaxf(mx0, fmaxf(sc[ni][0], sc[ni][1]));
            mx1 = fmaxf(mx1, fmaxf(sc[ni][2], sc[ni][3]));
        }
        mx0 = fmaxf(mx0, __shfl_xor_sync(0xffffffffu, mx0, 1));
        mx0 = fmaxf(mx0, __shfl_xor_sync(0xffffffffu, mx0, 2));
        mx1 = fmaxf(mx1, __shfl_xor_sync(0xffffffffu, mx1, 1));
        mx1 = fmaxf(mx1, __shfl_xor_sync(0xffffffffu, mx1, 2));
        const float nm0 = fmaxf(m0, mx0), nm1 = fmaxf(m1, mx1);
        const float al0 = __expf(m0 - nm0), al1 = __expf(m1 - nm1);
        m0 = nm0; m1 = nm1;

        float s0 = 0.f, s1 = 0.f;
        uint32_t pa[4][4];
        #pragma unroll
        for (int ni = 0; ni < 8; ni++) {
            const float p0 = __expf(sc[ni][0] - nm0);
            const float p1 = __expf(sc[ni][1] - nm0);
            const float p2 = __expf(sc[ni][2] - nm1);
            const float p3 = __expf(sc[ni][3] - nm1);
            s0 += p0 + p1; s1 += p2 + p3;
            const int kk = ni >> 1, w2 = (ni & 1) * 2;
            pa[kk][w2    ] = packh2(p0, p1);
            pa[kk][w2 + 1] = packh2(p2, p3);
        }
        s0 += __shfl_xor_sync(0xffffffffu, s0, 1);
        s0 += __shfl_xor_sync(0xffffffffu, s0, 2);
        s1 += __shfl_xor_sync(0xffffffffu, s1, 1);
        s1 += __shfl_xor_sync(0xffffffffu, s1, 2);
        l0 = l0 * al0 + s0;
        l1 = l1 * al1 + s1;
        #pragma unroll
        for (int ni = 0; ni < 8; ni++) {
            oac[ni][0] *= al0; oac[ni][1] *= al0;
            oac[ni][2] *= al1; oac[ni][3] *= al1;
        }

        #pragma unroll
        for (int kk = 0; kk < 4; kk++) {
            uint32_t bfr[8][2];
            #pragma unroll
            for (int nip = 0; nip < 4; nip++) {
                const uint32_t addr = smem_u32(&sV[16*kk + lm_r][nip*16 + lm_c]);
                asm volatile(
                    "ldmatrix.sync.aligned.m8n8.x4.trans.shared.b16 {%0,%1,%2,%3}, [%4];"
                    : "=r"(bfr[2*nip][0]), "=r"(bfr[2*nip][1]),
                      "=r"(bfr[2*nip+1][0]), "=r"(bfr[2*nip+1][1])
                    : "r"(addr));
            }
            #pragma unroll
            for (int ni = 0; ni < 8; ni++)
                mma_f16(oac[ni], pa[kk][0], pa[kk][1], pa[kk][2], pa[kk][3],
                        bfr[ni][0], bfr[ni][1]);
        }
    }

    const float il0 = 1.0f / l0, il1 = 1.0f / l1;
    const size_t row0 = (size_t)b * S_ + qt*128 + qrow + gr;
    __half* o0 = of + row0 * E_ + h*64;
    __half* o1 = o0 + (size_t)8 * E_;
    #pragma unroll
    for (int ni = 0; ni < 8; ni++) {
        *reinterpret_cast<uint32_t*>(o0 + ni*8 + tq*2) = packh2(oac[ni][0]*il0, oac[ni][1]*il0);
        *reinterpret_cast<uint32_t*>(o1 + ni*8 + tq*2) = packh2(oac[ni][2]*il1, oac[ni][3]*il1);
    }
}

// ============================================================
// launch — R12 structure: side stream converts wo/w13/w2 weights
// concurrently with rmsnorm -> qkv GEMM -> attention.
// ============================================================
extern "C" void kernel_launch(void* const* d_in, const int* in_sizes, int n_in,
                              void* d_out, int out_size)
{
    (void)in_sizes; (void)n_in; (void)out_size;
    const float* x     = (const float*)d_in[0];
    const float* fc    = (const float*)d_in[2];
    const float* w_qkv = (const float*)d_in[3];
    const float* w_o   = (const float*)d_in[4];
    const float* w1    = (const float*)d_in[5];
    const float* w2    = (const float*)d_in[6];
    const float* w3    = (const float*)d_in[7];
    const float* anw   = (const float*)d_in[8];
    const float* fnw   = (const float*)d_in[9];
    float* out = (float*)d_out;

    __half *wqkvh, *woh, *w13h, *w2h;
    __half *h, *qh, *kh, *vh, *o, *g, *act;
    float  *h2;
    cudaGetSymbolAddress((void**)&wqkvh, g_wqkvh);
    cudaGetSymbolAddress((void**)&woh,   g_woh);
    cudaGetSymbolAddress((void**)&w13h,  g_w13h);
    cudaGetSymbolAddress((void**)&w2h,   g_w2h);
    cudaGetSymbolAddress((void**)&h,     g_h);
    cudaGetSymbolAddress((void**)&qh,    g_qh);
    cudaGetSymbolAddress((void**)&kh,    g_kh);
    cudaGetSymbolAddress((void**)&vh,    g_vh);
    cudaGetSymbolAddress((void**)&o,     g_o);
    cudaGetSymbolAddress((void**)&h2,    g_h2);
    cudaGetSymbolAddress((void**)&g,     g_g);
    cudaGetSymbolAddress((void**)&act,   g_act);

    // Side stream + fork/join events (host objects; created per call, bounded leak).
    cudaStream_t s2;
    cudaEvent_t evFork, evJoin;
    cudaStreamCreateWithFlags(&s2, cudaStreamNonBlocking);
    cudaEventCreateWithFlags(&evFork, cudaEventDisableTiming);
    cudaEventCreateWithFlags(&evJoin, cudaEventDisableTiming);

    // fork: side stream inherits capture from the main (default) stream
    cudaEventRecord(evFork, 0);
    cudaStreamWaitEvent(s2, evFork, 0);

    // side stream: weights not needed until after attention
    f2h_kernel<<<(E_*E_)/2048, 256, 0, s2>>>(w_o, woh);
    f2h_w13_kernel<<<(F_*E_)/2048, 256, 0, s2>>>(w1, w13h, 0);
    f2h_w13_kernel<<<(F_*E_)/2048, 256, 0, s2>>>(w3, w13h, 1);
    f2h_kernel<<<(E_*F_)/2048, 256, 0, s2>>>(w2, w2h);
    cudaEventRecord(evJoin, s2);

    // main stream: qkv weight convert + norm + qkv GEMM(+rope) + attention
    f2h_kernel<<<(QKVN*E_)/2048, 256>>>(w_qkv, wqkvh);
    rmsnorm_kernel<<<M_, 256>>>(x, anw, h);
    hgemm16<1><<<dim3(QKVN/128, M_/128), 256>>>(h, wqkvh, nullptr, nullptr,
                                                fc, qh, kh, vh, M_, QKVN, E_);
    attn_mma_kernel<<<dim3(S_/128, H_, B_), 256>>>(qh, kh, vh, o);

    // join: remaining GEMMs need the side-stream weights
    cudaStreamWaitEvent(0, evJoin, 0);

    // h2 = x + o @ w_o^T
    hgemm16<0><<<dim3(E_/128, M_/128), 256>>>(o, woh, x, h2,
                                              nullptr, nullptr, nullptr, nullptr, M_, E_, E_);
    // ffn rmsnorm
    rmsnorm_kernel<<<M_, 256>>>(h2, fnw, g);
    // w13 GEMM + fused SwiGLU
    hgemm16<2><<<dim3((2*F_)/128, M_/128), 256>>>(g, w13h, nullptr, act,
                                                  nullptr, nullptr, nullptr, nullptr, M_, 2*F_, E_);
    // out = h2 + act @ w2^T
    hgemm16<0><<<dim3(E_/128, M_/128), 256>>>(act, w2h, h2, out,
                                              nullptr, nullptr, nullptr, nullptr, M_, E_, F_);
}

// round 15
// speedup vs baseline: 1.0126x; 1.0010x over previous
#include <cuda_runtime.h>
#include <cuda_fp16.h>
#include <cstdint>

// Problem constants
#define B_    2
#define S_    2048
#define E_    2048
#define H_    32
#define KH_   8
#define HD_   64
#define F_    8192
#define KV_   (KH_*HD_)      // 512
#define QKVN  (E_ + 2*KV_)   // 3072
#define M_    (B_*S_)        // 4096

// -------- scratch (device globals: allocation-free) --------
__device__ __half g_wqkvh[(size_t)QKVN*E_];
__device__ __half g_woh  [(size_t)E_*E_];
__device__ __half g_w13h [(size_t)2*F_*E_];   // rows interleaved: 2j=w1_j, 2j+1=w3_j
__device__ __half g_w2h  [(size_t)E_*F_];

__device__ __half g_h    [(size_t)M_*E_];
__device__ __half g_qh   [(size_t)B_*H_ *S_*HD_];
__device__ __half g_kh   [(size_t)B_*KH_*S_*HD_];
__device__ __half g_vh   [(size_t)B_*KH_*S_*HD_];
__device__ __half g_o    [(size_t)M_*E_];
__device__ float  g_h2   [(size_t)M_*E_];
__device__ __half g_g    [(size_t)M_*E_];
__device__ __half g_act  [(size_t)M_*F_];

__device__ __forceinline__ uint32_t smem_u32(const void* p) {
    uint32_t a;
    asm("{ .reg .u64 t; cvta.to.shared.u64 t, %1; cvt.u32.u64 %0, t; }" : "=r"(a) : "l"(p));
    return a;
}
__device__ __forceinline__ uint32_t packh2(float a, float b) {
    __half2 h = __floats2half2_rn(a, b);
    return *reinterpret_cast<uint32_t*>(&h);
}
__device__ __forceinline__ float2 unpackh2(uint32_t u) {
    __half2 h = *reinterpret_cast<__half2*>(&u);
    return __half22float2(h);
}

// ============================================================
// fp32 -> fp16 bulk convert; 8 elems/thread. n % 2048 == 0.
// ============================================================
__global__ __launch_bounds__(256) void f2h_kernel(
    const float* __restrict__ in, __half* __restrict__ out)
{
    const size_t i = ((size_t)blockIdx.x * 256 + threadIdx.x) * 8;
    float4 v0 = *reinterpret_cast<const float4*>(in + i);
    float4 v1 = *reinterpret_cast<const float4*>(in + i + 4);
    uint4 o = make_uint4(packh2(v0.x, v0.y), packh2(v0.z, v0.w),
                         packh2(v1.x, v1.y), packh2(v1.z, v1.w));
    *reinterpret_cast<uint4*>(out + i) = o;
}

// fp32 -> fp16, both w1 and w3 rows interleaved into out (row 2j / 2j+1)
__global__ __launch_bounds__(256) void f2h_w13_kernel(
    const float* __restrict__ w1, const float* __restrict__ w3,
    __half* __restrict__ out)
{
    const size_t i = ((size_t)blockIdx.x * 256 + threadIdx.x) * 8;
    float4 a0 = *reinterpret_cast<const float4*>(w1 + i);
    float4 a1 = *reinterpret_cast<const float4*>(w1 + i + 4);
    float4 b0 = *reinterpret_cast<const float4*>(w3 + i);
    float4 b1 = *reinterpret_cast<const float4*>(w3 + i + 4);
    const size_t row = i >> 11;            // / E_
    const size_t col = i & (E_ - 1);
    __half* d1 = out + ((row << 1) << 11) + col;
    __half* d3 = d1 + E_;
    *reinterpret_cast<uint4*>(d1) = make_uint4(packh2(a0.x, a0.y), packh2(a0.z, a0.w),
                                               packh2(a1.x, a1.y), packh2(a1.z, a1.w));
    *reinterpret_cast<uint4*>(d3) = make_uint4(packh2(b0.x, b0.y), packh2(b0.z, b0.w),
                                               packh2(b1.x, b1.y), packh2(b1.z, b1.w));
}

// ============================================================
// RMSNorm: fp32 in, fp16 out. one block per row of 2048
// ============================================================
__global__ __launch_bounds__(256) void rmsnorm_kernel(
    const float* __restrict__ x, const float* __restrict__ w, __half* __restrict__ o)
{
    const int tid = threadIdx.x;
    const size_t base = (size_t)blockIdx.x * E_;
    float4 v0 = *reinterpret_cast<const float4*>(x + base + tid*4);
    float4 v1 = *reinterpret_cast<const float4*>(x + base + 1024 + tid*4);
    float ss = v0.x*v0.x + v0.y*v0.y + v0.z*v0.z + v0.w*v0.w
             + v1.x*v1.x + v1.y*v1.y + v1.z*v1.z + v1.w*v1.w;
    #pragma unroll
    for (int off = 16; off; off >>= 1) ss += __shfl_xor_sync(0xffffffffu, ss, off);
    __shared__ float sred[8];
    if ((tid & 31) == 0) sred[tid >> 5] = ss;
    __syncthreads();
    float tot = 0.f;
    #pragma unroll
    for (int i = 0; i < 8; i++) tot += sred[i];
    float inv = rsqrtf(tot * (1.0f / (float)E_) + 1e-5f);
    float4 w0 = *reinterpret_cast<const float4*>(w + tid*4);
    float4 w1 = *reinterpret_cast<const float4*>(w + 1024 + tid*4);
    uint2 o0 = make_uint2(packh2(v0.x*inv*w0.x, v0.y*inv*w0.y),
                          packh2(v0.z*inv*w0.z, v0.w*inv*w0.w));
    uint2 o1 = make_uint2(packh2(v1.x*inv*w1.x, v1.y*inv*w1.y),
                          packh2(v1.z*inv*w1.z, v1.w*inv*w1.w));
    *reinterpret_cast<uint2*>(o + base + tid*4)        = o0;
    *reinterpret_cast<uint2*>(o + base + 1024 + tid*4) = o1;
}

// -------- fp16 mma --------
__device__ __forceinline__ void mma_f16(float* c,
    uint32_t a0, uint32_t a1, uint32_t a2, uint32_t a3,
    uint32_t b0, uint32_t b1)
{
    asm volatile(
        "mma.sync.aligned.m16n8k16.row.col.f32.f16.f16.f32 "
        "{%0,%1,%2,%3}, {%4,%5,%6,%7}, {%8,%9}, {%0,%1,%2,%3};"
        : "+f"(c[0]), "+f"(c[1]), "+f"(c[2]), "+f"(c[3])
        : "r"(a0), "r"(a1), "r"(a2), "r"(a3), "r"(b0), "r"(b1));
}

// interleave two uint4 (halves k0..7, k8..15) into perm slot order
__device__ __forceinline__ void perm_sts(__half* rowp, uint4 lo, uint4 hi) {
    *reinterpret_cast<uint4*>(rowp)     = make_uint4(lo.x, hi.x, lo.y, hi.y);
    *reinterpret_cast<uint4*>(rowp + 8) = make_uint4(lo.z, hi.z, lo.w, hi.w);
}

// RoPE rotate-and-scatter for one fp32 pair (c even), row in [0,M)
__device__ __forceinline__ void rope_store(float2 v, int row, int c,
    const float* __restrict__ fc,
    __half* __restrict__ qp, __half* __restrict__ kp, __half* __restrict__ vp)
{
    const int b = row >> 11, s = row & (S_ - 1);
    if (c < E_) {
        const int hh = c >> 6, d = c & 63;
        const float cs = fc[s*64 + d], sn = fc[s*64 + d + 1];
        *reinterpret_cast<uint32_t*>(qp + ((((size_t)b*H_ + hh)*S_ + s) << 6) + d) =
            packh2((v.x*cs - v.y*sn) * 0.125f, (v.y*cs + v.x*sn) * 0.125f);
    } else if (c < E_ + KV_) {
        const int kc = c - E_, kh = kc >> 6, d = kc & 63;
        const float cs = fc[s*64 + d], sn = fc[s*64 + d + 1];
        *reinterpret_cast<uint32_t*>(kp + ((((size_t)b*KH_ + kh)*S_ + s) << 6) + d) =
            packh2(v.x*cs - v.y*sn, v.y*cs + v.x*sn);
    } else {
        const int vc = c - E_ - KV_, kh = vc >> 6, d = vc & 63;
        *reinterpret_cast<uint32_t*>(vp + ((((size_t)b*KH_ + kh)*S_ + s) << 6) + d) =
            packh2(v.x, v.y);
    }
}

// ============================================================
// FP16-in tensor-core GEMM NT (proven R12/R14 form):
// Block 128x128, K-tile 32, 256 thr (8 warps 4Mx2N), warp 32x64.
// MODE 0: C fp32 = A*B^T + Res
// MODE 1: rope epilogue -> q/k/v fp16 (qkv GEMM)
// MODE 2: swiglu epilogue -> act fp16 (w13 GEMM, interleaved rows)
// ============================================================
template<int MODE>
__global__ __launch_bounds__(256, 2) void hgemm16(
    const __half* __restrict__ A, const __half* __restrict__ B,
    const float* __restrict__ Res, void* __restrict__ Cv,
    const float* __restrict__ fcp,
    __half* __restrict__ qp, __half* __restrict__ kp, __half* __restrict__ vp,
    int M, int N, int K)
{
    __shared__ __align__(16) __half As[2][2][128][16];
    __shared__ __align__(16) __half Bs[2][2][128][16];

    const int tid  = threadIdx.x;
    const int lane = tid & 31;
    const int warp = tid >> 5;
    const int bm = blockIdx.y * 128;
    const int bn = blockIdx.x * 128;

    const int m0 = (warp & 3) * 32;
    const int n0 = (warp >> 2) * 64;

    const int r_l  = tid >> 1;    // 0..127
    const int kk_l = tid & 1;     // 0..1
    const __half* Ag = A + (size_t)(bm + r_l) * K + kk_l * 16;
    const __half* Bg = B + (size_t)(bn + r_l) * K + kk_l * 16;

    float acc[2][8][4];
    #pragma unroll
    for (int i = 0; i < 2; i++)
        #pragma unroll
        for (int j = 0; j < 8; j++)
            acc[i][j][0] = acc[i][j][1] = acc[i][j][2] = acc[i][j][3] = 0.f;

    {
        uint4 a0 = *reinterpret_cast<const uint4*>(Ag);
        uint4 a1 = *reinterpret_cast<const uint4*>(Ag + 8);
        uint4 b0 = *reinterpret_cast<const uint4*>(Bg);
        uint4 b1 = *reinterpret_cast<const uint4*>(Bg + 8);
        perm_sts(&As[0][kk_l][r_l][0], a0, a1);
        perm_sts(&Bs[0][kk_l][r_l][0], b0, b1);
    }
    __syncthreads();

    const int gr = lane >> 2;
    const int tq = lane & 3;
    const int KT = K >> 5;

    for (int kt = 0; kt < KT; ++kt) {
        const int buf = kt & 1;
        const bool pf = (kt + 1 < KT);
        uint4 pa0, pa1, pb0, pb1;
        if (pf) {
            const __half* Ap = Ag + (size_t)(kt + 1) * 32;
            const __half* Bp = Bg + (size_t)(kt + 1) * 32;
            pa0 = *reinterpret_cast<const uint4*>(Ap);
            pa1 = *reinterpret_cast<const uint4*>(Ap + 8);
            pb0 = *reinterpret_cast<const uint4*>(Bp);
            pb1 = *reinterpret_cast<const uint4*>(Bp + 8);
        }

        #pragma unroll
        for (int kk = 0; kk < 2; ++kk) {
            uint2 ax[2], ay[2];
            #pragma unroll
            for (int mi = 0; mi < 2; mi++) {
                const int r = m0 + mi * 16 + gr;
                ax[mi] = *reinterpret_cast<const uint2*>(&As[buf][kk][r    ][tq * 4]);
                ay[mi] = *reinterpret_cast<const uint2*>(&As[buf][kk][r + 8][tq * 4]);
            }
            #pragma unroll
            for (int ni = 0; ni < 8; ni++) {
                const uint2 bv = *reinterpret_cast<const uint2*>(&Bs[buf][kk][n0 + ni * 8 + gr][tq * 4]);
                #pragma unroll
                for (int mi = 0; mi < 2; mi++)
                    mma_f16(acc[mi][ni], ax[mi].x, ay[mi].x, ax[mi].y, ay[mi].y, bv.x, bv.y);
            }
        }

        if (pf) {
            const int nxt = buf ^ 1;
            perm_sts(&As[nxt][kk_l][r_l][0], pa0, pa1);
            perm_sts(&Bs[nxt][kk_l][r_l][0], pb0, pb1);
            __syncthreads();
        }
    }

    // ---- epilogue ----
    const int gc = tq * 2;
    #pragma unroll
    for (int mi = 0; mi < 2; mi++) {
        #pragma unroll
        for (int ni = 0; ni < 8; ni++) {
            const int r = bm + m0 + mi * 16 + gr;
            const int c = bn + n0 + ni * 8 + gc;
            float2 lo = make_float2(acc[mi][ni][0], acc[mi][ni][1]);
            float2 hi = make_float2(acc[mi][ni][2], acc[mi][ni][3]);
            if (MODE == 0) {
                float2 rlo = *reinterpret_cast<const float2*>(Res + (size_t)r * N + c);
                float2 rhi = *reinterpret_cast<const float2*>(Res + (size_t)(r + 8) * N + c);
                lo.x += rlo.x; lo.y += rlo.y;
                hi.x += rhi.x; hi.y += rhi.y;
                float* C = (float*)Cv;
                *reinterpret_cast<float2*>(C + (size_t)r * N + c)       = lo;
                *reinterpret_cast<float2*>(C + (size_t)(r + 8) * N + c) = hi;
            } else if (MODE == 1) {
                rope_store(lo, r,     c, fcp, qp, kp, vp);
                rope_store(hi, r + 8, c, fcp, qp, kp, vp);
            } else {
                const int j = c >> 1;
                const float a0 = lo.x * lo.y / (1.f + __expf(-lo.x));
                const float a1 = hi.x * hi.y / (1.f + __expf(-hi.x));
                __half* act = (__half*)Cv;
                act[(size_t)r * F_ + j]       = __float2half(a0);
                act[(size_t)(r + 8) * F_ + j] = __float2half(a1);
            }
        }
    }
}

// ============================================================
// Flash attention, fp16 mma, causal, GQA 4:1. fp16 output.
// 128 q-rows x 64 k-cols per block, 256 thr (8 warps x 16 rows).
// Register-staged K/V prefetch to hide LDG latency (1 CTA/SM).
// ============================================================
__global__ __launch_bounds__(256) void attn_mma_kernel(
    const __half* __restrict__ qr, const __half* __restrict__ kr,
    const __half* __restrict__ vr, __half* __restrict__ of)
{
    __shared__ __align__(16) __half sQ[4][128][16];
    __shared__ __align__(16) __half sK[4][64][16];
    __shared__ __align__(16) __half sV[64][72];

    const int tid  = threadIdx.x;
    const int lane = tid & 31, warp = tid >> 5;
    const int qt = blockIdx.x, h = blockIdx.y, b = blockIdx.z;
    const int kvh = h >> 2;
    const __half* Q = qr + (((size_t)(b*H_ + h)) * S_ + qt*128) * HD_;
    const __half* K = kr + ((size_t)(b*KH_ + kvh)) * S_ * HD_;
    const __half* V = vr + ((size_t)(b*KH_ + kvh)) * S_ * HD_;

    // loader coords (fixed per thread): 2 iters x (r, seg)
    const int lr0 = tid >> 3,           lseg0 = tid & 7;
    const int lr1 = (tid + 256) >> 3,   lseg1 = (tid + 256) & 7;

    #pragma unroll
    for (int it = 0; it < 4; it++) {
        const int f = tid + it*256;
        const int r = f >> 3, seg = f & 7;
        const int g = seg >> 1, hp = seg & 1;
        uint4 v4 = *reinterpret_cast<const uint4*>(Q + (size_t)r*64 + seg*8);
        uint32_t* p = reinterpret_cast<uint32_t*>(&sQ[g][r][0]);
        p[hp] = v4.x; p[hp+2] = v4.y; p[hp+4] = v4.z; p[hp+6] = v4.w;
    }

    const int gr = lane >> 2;
    const int tq = lane & 3;
    const int qrow = warp * 16;
    const int lm_r = (lane & 7) + ((lane >> 3) & 1) * 8;
    const int lm_c = ((lane >> 4) & 1) * 8;

    float m0 = -1e30f, m1 = -1e30f, l0 = 0.f, l1 = 0.f;
    float oac[8][4];
    #pragma unroll
    for (int i = 0; i < 8; i++)
        oac[i][0] = oac[i][1] = oac[i][2] = oac[i][3] = 0.f;

    const int KTILES = 2*qt + 2;

    // prefetch tile 0 into registers
    uint4 pk0 = *reinterpret_cast<const uint4*>(K + (size_t)lr0*64 + lseg0*8);
    uint4 pv0 = *reinterpret_cast<const uint4*>(V + (size_t)lr0*64 + lseg0*8);
    uint4 pk1 = *reinterpret_cast<const uint4*>(K + (size_t)lr1*64 + lseg1*8);
    uint4 pv1 = *reinterpret_cast<const uint4*>(V + (size_t)lr1*64 + lseg1*8);

    for (int kt = 0; kt < KTILES; ++kt) {
        __syncthreads();   // prior tile's smem reads complete
        {
            const int g0 = lseg0 >> 1, hp0 = lseg0 & 1;
            uint32_t* p = reinterpret_cast<uint32_t*>(&sK[g0][lr0][0]);
            p[hp0] = pk0.x; p[hp0+2] = pk0.y; p[hp0+4] = pk0.z; p[hp0+6] = pk0.w;
            *reinterpret_cast<uint4*>(&sV[lr0][lseg0*8]) = pv0;
            const int g1 = lseg1 >> 1, hp1 = lseg1 & 1;
            uint32_t* q = reinterpret_cast<uint32_t*>(&sK[g1][lr1][0]);
            q[hp1] = pk1.x; q[hp1+2] = pk1.y; q[hp1+4] = pk1.z; q[hp1+6] = pk1.w;
            *reinterpret_cast<uint4*>(&sV[lr1][lseg1*8]) = pv1;
        }
        __syncthreads();

        if (kt + 1 < KTILES) {   // prefetch next tile during compute
            const __half* Kn = K + ((size_t)(kt+1)*64)*64;
            const __half* Vn = V + ((size_t)(kt+1)*64)*64;
            pk0 = *reinterpret_cast<const uint4*>(Kn + (size_t)lr0*64 + lseg0*8);
            pv0 = *reinterpret_cast<const uint4*>(Vn + (size_t)lr0*64 + lseg0*8);
            pk1 = *reinterpret_cast<const uint4*>(Kn + (size_t)lr1*64 + lseg1*8);
            pv1 = *reinterpret_cast<const uint4*>(Vn + (size_t)lr1*64 + lseg1*8);
        }

        float sc[8][4];
        #pragma unroll
        for (int i = 0; i < 8; i++)
            sc[i][0] = sc[i][1] = sc[i][2] = sc[i][3] = 0.f;
        #pragma unroll
        for (int kk = 0; kk < 4; kk++) {
            const uint2 alo = *reinterpret_cast<const uint2*>(&sQ[kk][qrow + gr    ][tq*4]);
            const uint2 ahi = *reinterpret_cast<const uint2*>(&sQ[kk][qrow + gr + 8][tq*4]);
            #pragma unroll
            for (int ni = 0; ni < 8; ni++) {
                const uint2 bv = *reinterpret_cast<const uint2*>(&sK[kk][ni*8 + gr][tq*4]);
                mma_f16(sc[ni], alo.x, ahi.x, alo.y, ahi.y, bv.x, bv.y);
            }
        }

        if (kt >= 2*qt) {
            const int r0g = qt*128 + qrow + gr;
            const int r1g = r0g + 8;
            #pragma unroll
            for (int ni = 0; ni < 8; ni++) {
                const int c0 = kt*64 + ni*8 + tq*2, c1 = c0 + 1;
                if (c0 > r0g) sc[ni][0] = -1e30f;
                if (c1 > r0g) sc[ni][1] = -1e30f;
                if (c0 > r1g) sc[ni][2] = -1e30f;
                if (c1 > r1g) sc[ni][3] = -1e30f;
            }
        }

        float mx0 = -1e30f, mx1 = -1e30f;
        #pragma unroll
        for (int ni = 0; ni < 8; ni++) {
            mx0 = fmaxf(mx0, fmaxf(sc[ni][0], sc[ni][1]));
            mx1 = fmaxf(mx1, fmaxf(sc[ni][2], sc[ni][3]));
        }
        mx0 = fmaxf(mx0, __shfl_xor_sync(0xffffffffu, mx0, 1));
        mx0 = fmaxf(mx0, __shfl_xor_sync(0xffffffffu, mx0, 2));
        mx1 = fmaxf(mx1, __shfl_xor_sync(0xffffffffu, mx1, 1));
        mx1 = fmaxf(mx1, __shfl_xor_sync(0xffffffffu, mx1, 2));
        const float nm0 = fmaxf(m0, mx0), nm1 = fmaxf(m1, mx1);
        const float al0 = __expf(m0 - nm0), al1 = __expf(m1 - nm1);
        m0 = nm0; m1 = nm1;

        float s0 = 0.f, s1 = 0.f;
        uint32_t pa[4][4];
        #pragma unroll
        for (int ni = 0; ni < 8; ni++) {
            const float p0 = __expf(sc[ni][0] - nm0);
            const float p1 = __expf(sc[ni][1] - nm0);
            const float p2 = __expf(sc[ni][2] - nm1);
            const float p3 = __expf(sc[ni][3] - nm1);
            s0 += p0 + p1; s1 += p2 + p3;
            const int kk = ni >> 1, w2 = (ni & 1) * 2;
            pa[kk][w2    ] = packh2(p0, p1);
            pa[kk][w2 + 1] = packh2(p2, p3);
        }
        s0 += __shfl_xor_sync(0xffffffffu, s0, 1);
        s0 += __shfl_xor_sync(0xffffffffu, s0, 2);
        s1 += __shfl_xor_sync(0xffffffffu, s1, 1);
        s1 += __shfl_xor_sync(0xffffffffu, s1, 2);
        l0 = l0 * al0 + s0;
        l1 = l1 * al1 + s1;
        #pragma unroll
        for (int ni = 0; ni < 8; ni++) {
            oac[ni][0] *= al0; oac[ni][1] *= al0;
            oac[ni][2] *= al1; oac[ni][3] *= al1;
        }

        #pragma unroll
        for (int kk = 0; kk < 4; kk++) {
            uint32_t bfr[8][2];
            #pragma unroll
            for (int nip = 0; nip < 4; nip++) {
                const uint32_t addr = smem_u32(&sV[16*kk + lm_r][nip*16 + lm_c]);
                asm volatile(
                    "ldmatrix.sync.aligned.m8n8.x4.trans.shared.b16 {%0,%1,%2,%3}, [%4];"
                    : "=r"(bfr[2*nip][0]), "=r"(bfr[2*nip][1]),
                      "=r"(bfr[2*nip+1][0]), "=r"(bfr[2*nip+1][1])
                    : "r"(addr));
            }
            #pragma unroll
            for (int ni = 0; ni < 8; ni++)
                mma_f16(oac[ni], pa[kk][0], pa[kk][1], pa[kk][2], pa[kk][3],
                        bfr[ni][0], bfr[ni][1]);
        }
    }

    const float il0 = 1.0f / l0, il1 = 1.0f / l1;
    const size_t row0 = (size_t)b * S_ + qt*128 + qrow + gr;
    __half* o0 = of + row0 * E_ + h*64;
    __half* o1 = o0 + (size_t)8 * E_;
    #pragma unroll
    for (int ni = 0; ni < 8; ni++) {
        *reinterpret_cast<uint32_t*>(o0 + ni*8 + tq*2) = packh2(oac[ni][0]*il0, oac[ni][1]*il0);
        *reinterpret_cast<uint32_t*>(o1 + ni*8 + tq*2) = packh2(oac[ni][2]*il1, oac[ni][3]*il1);
    }
}

// ============================================================
// launch — side stream converts wqkv first (joined before qkv GEMM),
// then wo/w13/w2 (joined before the wo GEMM).
// ============================================================
extern "C" void kernel_launch(void* const* d_in, const int* in_sizes, int n_in,
                              void* d_out, int out_size)
{
    (void)in_sizes; (void)n_in; (void)out_size;
    const float* x     = (const float*)d_in[0];
    const float* fc    = (const float*)d_in[2];
    const float* w_qkv = (const float*)d_in[3];
    const float* w_o   = (const float*)d_in[4];
    const float* w1    = (const float*)d_in[5];
    const float* w2    = (const float*)d_in[6];
    const float* w3    = (const float*)d_in[7];
    const float* anw   = (const float*)d_in[8];
    const float* fnw   = (const float*)d_in[9];
    float* out = (float*)d_out;

    __half *wqkvh, *woh, *w13h, *w2h;
    __half *h, *qh, *kh, *vh, *o, *g, *act;
    float  *h2;
    cudaGetSymbolAddress((void**)&wqkvh, g_wqkvh);
    cudaGetSymbolAddress((void**)&woh,   g_woh);
    cudaGetSymbolAddress((void**)&w13h,  g_w13h);
    cudaGetSymbolAddress((void**)&w2h,   g_w2h);
    cudaGetSymbolAddress((void**)&h,     g_h);
    cudaGetSymbolAddress((void**)&qh,    g_qh);
    cudaGetSymbolAddress((void**)&kh,    g_kh);
    cudaGetSymbolAddress((void**)&vh,    g_vh);
    cudaGetSymbolAddress((void**)&o,     g_o);
    cudaGetSymbolAddress((void**)&h2,    g_h2);
    cudaGetSymbolAddress((void**)&g,     g_g);
    cudaGetSymbolAddress((void**)&act,   g_act);

    // Side stream + fork/join events (host objects; created per call, bounded leak).
    cudaStream_t s2;
    cudaEvent_t evFork, evQkvW, evJoin;
    cudaStreamCreateWithFlags(&s2, cudaStreamNonBlocking);
    cudaEventCreateWithFlags(&evFork, cudaEventDisableTiming);
    cudaEventCreateWithFlags(&evQkvW, cudaEventDisableTiming);
    cudaEventCreateWithFlags(&evJoin, cudaEventDisableTiming);

    // fork
    cudaEventRecord(evFork, 0);
    cudaStreamWaitEvent(s2, evFork, 0);

    // side stream: qkv weights first (overlaps main-stream rmsnorm), then the rest
    f2h_kernel<<<(QKVN*E_)/2048, 256, 0, s2>>>(w_qkv, wqkvh);
    cudaEventRecord(evQkvW, s2);
    f2h_kernel<<<(E_*E_)/2048, 256, 0, s2>>>(w_o, woh);
    f2h_w13_kernel<<<(F_*E_)/2048, 256, 0, s2>>>(w1, w3, w13h);
    f2h_kernel<<<(E_*F_)/2048, 256, 0, s2>>>(w2, w2h);
    cudaEventRecord(evJoin, s2);

    // main stream
    rmsnorm_kernel<<<M_, 256>>>(x, anw, h);
    cudaStreamWaitEvent(0, evQkvW, 0);
    hgemm16<1><<<dim3(QKVN/128, M_/128), 256>>>(h, wqkvh, nullptr, nullptr,
                                                fc, qh, kh, vh, M_, QKVN, E_);
    attn_mma_kernel<<<dim3(S_/128, H_, B_), 256>>>(qh, kh, vh, o);

    // join: remaining GEMMs need the side-stream weights
    cudaStreamWaitEvent(0, evJoin, 0);

    // h2 = x + o @ w_o^T
    hgemm16<0><<<dim3(E_/128, M_/128), 256>>>(o, woh, x, h2,
                                              nullptr, nullptr, nullptr, nullptr, M_, E_, E_);
    // ffn rmsnorm
    rmsnorm_kernel<<<M_, 256>>>(h2, fnw, g);
    // w13 GEMM + fused SwiGLU
    hgemm16<2><<<dim3((2*F_)/128, M_/128), 256>>>(g, w13h, nullptr, act,
                                                  nullptr, nullptr, nullptr, nullptr, M_, 2*F_, E_);
    // out = h2 + act @ w2^T
    hgemm16<0><<<dim3(E_/128, M_/128), 256>>>(act, w2h, h2, out,
                                              nullptr, nullptr, nullptr, nullptr, M_, E_, F_);
}

// round 16
// speedup vs baseline: 1.0307x; 1.0179x over previous
#include <cuda_runtime.h>
#include <cuda_fp16.h>
#include <cstdint>

// Problem constants
#define B_    2
#define S_    2048
#define E_    2048
#define H_    32
#define KH_   8
#define HD_   64
#define F_    8192
#define KV_   (KH_*HD_)      // 512
#define QKVN  (E_ + 2*KV_)   // 3072
#define M_    (B_*S_)        // 4096

// -------- scratch (device globals: allocation-free) --------
__device__ __half g_wqkvh[(size_t)QKVN*E_];
__device__ __half g_woh  [(size_t)E_*E_];
__device__ __half g_w13h [(size_t)2*F_*E_];   // rows interleaved: 2j=w1_j, 2j+1=w3_j
__device__ __half g_w2h  [(size_t)E_*F_];

__device__ __half g_h    [(size_t)M_*E_];
__device__ __half g_qh   [(size_t)B_*H_ *S_*HD_];
__device__ __half g_kh   [(size_t)B_*KH_*S_*HD_];
__device__ __half g_vh   [(size_t)B_*KH_*S_*HD_];
__device__ __half g_o    [(size_t)M_*E_];
__device__ float  g_h2   [(size_t)M_*E_];
__device__ __half g_g    [(size_t)M_*E_];
__device__ __half g_act  [(size_t)M_*F_];

__device__ __forceinline__ uint32_t smem_u32(const void* p) {
    uint32_t a;
    asm("{ .reg .u64 t; cvta.to.shared.u64 t, %1; cvt.u32.u64 %0, t; }" : "=r"(a) : "l"(p));
    return a;
}
__device__ __forceinline__ uint32_t packh2(float a, float b) {
    __half2 h = __floats2half2_rn(a, b);
    return *reinterpret_cast<uint32_t*>(&h);
}
__device__ __forceinline__ float2 unpackh2(uint32_t u) {
    __half2 h = *reinterpret_cast<__half2*>(&u);
    return __half22float2(h);
}

// ============================================================
// fp32 -> fp16 bulk convert; 8 elems/thread. n % 2048 == 0.
// ============================================================
__global__ __launch_bounds__(256) void f2h_kernel(
    const float* __restrict__ in, __half* __restrict__ out)
{
    const size_t i = ((size_t)blockIdx.x * 256 + threadIdx.x) * 8;
    float4 v0 = *reinterpret_cast<const float4*>(in + i);
    float4 v1 = *reinterpret_cast<const float4*>(in + i + 4);
    uint4 o = make_uint4(packh2(v0.x, v0.y), packh2(v0.z, v0.w),
                         packh2(v1.x, v1.y), packh2(v1.z, v1.w));
    *reinterpret_cast<uint4*>(out + i) = o;
}

// fp32 -> fp16, both w1 and w3 rows interleaved into out (row 2j / 2j+1)
__global__ __launch_bounds__(256) void f2h_w13_kernel(
    const float* __restrict__ w1, const float* __restrict__ w3,
    __half* __restrict__ out)
{
    const size_t i = ((size_t)blockIdx.x * 256 + threadIdx.x) * 8;
    float4 a0 = *reinterpret_cast<const float4*>(w1 + i);
    float4 a1 = *reinterpret_cast<const float4*>(w1 + i + 4);
    float4 b0 = *reinterpret_cast<const float4*>(w3 + i);
    float4 b1 = *reinterpret_cast<const float4*>(w3 + i + 4);
    const size_t row = i >> 11;            // / E_
    const size_t col = i & (E_ - 1);
    __half* d1 = out + ((row << 1) << 11) + col;
    __half* d3 = d1 + E_;
    *reinterpret_cast<uint4*>(d1) = make_uint4(packh2(a0.x, a0.y), packh2(a0.z, a0.w),
                                               packh2(a1.x, a1.y), packh2(a1.z, a1.w));
    *reinterpret_cast<uint4*>(d3) = make_uint4(packh2(b0.x, b0.y), packh2(b0.z, b0.w),
                                               packh2(b1.x, b1.y), packh2(b1.z, b1.w));
}

// ============================================================
// RMSNorm: fp32 in, fp16 out. one block per row of 2048
// ============================================================
__global__ __launch_bounds__(256) void rmsnorm_kernel(
    const float* __restrict__ x, const float* __restrict__ w, __half* __restrict__ o)
{
    const int tid = threadIdx.x;
    const size_t base = (size_t)blockIdx.x * E_;
    float4 v0 = *reinterpret_cast<const float4*>(x + base + tid*4);
    float4 v1 = *reinterpret_cast<const float4*>(x + base + 1024 + tid*4);
    float ss = v0.x*v0.x + v0.y*v0.y + v0.z*v0.z + v0.w*v0.w
             + v1.x*v1.x + v1.y*v1.y + v1.z*v1.z + v1.w*v1.w;
    #pragma unroll
    for (int off = 16; off; off >>= 1) ss += __shfl_xor_sync(0xffffffffu, ss, off);
    __shared__ float sred[8];
    if ((tid & 31) == 0) sred[tid >> 5] = ss;
    __syncthreads();
    float tot = 0.f;
    #pragma unroll
    for (int i = 0; i < 8; i++) tot += sred[i];
    float inv = rsqrtf(tot * (1.0f / (float)E_) + 1e-5f);
    float4 w0 = *reinterpret_cast<const float4*>(w + tid*4);
    float4 w1 = *reinterpret_cast<const float4*>(w + 1024 + tid*4);
    uint2 o0 = make_uint2(packh2(v0.x*inv*w0.x, v0.y*inv*w0.y),
                          packh2(v0.z*inv*w0.z, v0.w*inv*w0.w));
    uint2 o1 = make_uint2(packh2(v1.x*inv*w1.x, v1.y*inv*w1.y),
                          packh2(v1.z*inv*w1.z, v1.w*inv*w1.w));
    *reinterpret_cast<uint2*>(o + base + tid*4)        = o0;
    *reinterpret_cast<uint2*>(o + base + 1024 + tid*4) = o1;
}

// -------- fp16 mma --------
__device__ __forceinline__ void mma_f16(float* c,
    uint32_t a0, uint32_t a1, uint32_t a2, uint32_t a3,
    uint32_t b0, uint32_t b1)
{
    asm volatile(
        "mma.sync.aligned.m16n8k16.row.col.f32.f16.f16.f32 "
        "{%0,%1,%2,%3}, {%4,%5,%6,%7}, {%8,%9}, {%0,%1,%2,%3};"
        : "+f"(c[0]), "+f"(c[1]), "+f"(c[2]), "+f"(c[3])
        : "r"(a0), "r"(a1), "r"(a2), "r"(a3), "r"(b0), "r"(b1));
}

// interleave two uint4 (halves k0..7, k8..15) into perm slot order
__device__ __forceinline__ void perm_sts(__half* rowp, uint4 lo, uint4 hi) {
    *reinterpret_cast<uint4*>(rowp)     = make_uint4(lo.x, hi.x, lo.y, hi.y);
    *reinterpret_cast<uint4*>(rowp + 8) = make_uint4(lo.z, hi.z, lo.w, hi.w);
}

// RoPE rotate-and-scatter for one fp32 pair (c even), row in [0,M)
__device__ __forceinline__ void rope_store(float2 v, int row, int c,
    const float* __restrict__ fc,
    __half* __restrict__ qp, __half* __restrict__ kp, __half* __restrict__ vp)
{
    const int b = row >> 11, s = row & (S_ - 1);
    if (c < E_) {
        const int hh = c >> 6, d = c & 63;
        const float cs = fc[s*64 + d], sn = fc[s*64 + d + 1];
        *reinterpret_cast<uint32_t*>(qp + ((((size_t)b*H_ + hh)*S_ + s) << 6) + d) =
            packh2((v.x*cs - v.y*sn) * 0.125f, (v.y*cs + v.x*sn) * 0.125f);
    } else if (c < E_ + KV_) {
        const int kc = c - E_, kh = kc >> 6, d = kc & 63;
        const float cs = fc[s*64 + d], sn = fc[s*64 + d + 1];
        *reinterpret_cast<uint32_t*>(kp + ((((size_t)b*KH_ + kh)*S_ + s) << 6) + d) =
            packh2(v.x*cs - v.y*sn, v.y*cs + v.x*sn);
    } else {
        const int vc = c - E_ - KV_, kh = vc >> 6, d = vc & 63;
        *reinterpret_cast<uint32_t*>(vp + ((((size_t)b*KH_ + kh)*S_ + s) << 6) + d) =
            packh2(v.x, v.y);
    }
}

// ============================================================
// FP16-in tensor-core GEMM NT, 4-stage smem ring, 2 k-tiles per
// sync (halved barrier count vs the 2-stage version).
// Block 128x128, K-tile 32, 256 thr (8 warps 4Mx2N), warp 32x64.
// Dynamic smem 64KB: stage s at s*16KB (A 8KB, B 8KB).
// Requires KT even (K % 64 == 0).
// MODE 0: C fp32 = A*B^T + Res
// MODE 1: rope epilogue -> q/k/v fp16
// MODE 2: swiglu epilogue -> act fp16 (interleaved w13 rows)
// ============================================================
template<int MODE>
__global__ __launch_bounds__(256, 2) void hgemm16(
    const __half* __restrict__ A, const __half* __restrict__ B,
    const float* __restrict__ Res, void* __restrict__ Cv,
    const float* __restrict__ fcp,
    __half* __restrict__ qp, __half* __restrict__ kp, __half* __restrict__ vp,
    int M, int N, int K)
{
    extern __shared__ __align__(16) char dsm[];

    const int tid  = threadIdx.x;
    const int lane = tid & 31;
    const int warp = tid >> 5;
    const int bm = blockIdx.y * 128;
    const int bn = blockIdx.x * 128;

    const int m0 = (warp & 3) * 32;
    const int n0 = (warp >> 2) * 64;

    const int r_l  = tid >> 1;    // 0..127
    const int kk_l = tid & 1;     // 0..1
    const __half* Ag = A + (size_t)(bm + r_l) * K + kk_l * 16;
    const __half* Bg = B + (size_t)(bn + r_l) * K + kk_l * 16;
    const uint32_t soff = (uint32_t)(kk_l * 128 + r_l) * 32u;   // bytes into a stage half

    float acc[2][8][4];
    #pragma unroll
    for (int i = 0; i < 2; i++)
        #pragma unroll
        for (int j = 0; j < 8; j++)
            acc[i][j][0] = acc[i][j][1] = acc[i][j][2] = acc[i][j][3] = 0.f;

    // prologue: tiles 0 and 1 into stages 0, 1
    #pragma unroll
    for (int s = 0; s < 2; s++) {
        const __half* Ap = Ag + s * 32;
        const __half* Bp = Bg + s * 32;
        uint4 a0 = *reinterpret_cast<const uint4*>(Ap);
        uint4 a1 = *reinterpret_cast<const uint4*>(Ap + 8);
        uint4 b0 = *reinterpret_cast<const uint4*>(Bp);
        uint4 b1 = *reinterpret_cast<const uint4*>(Bp + 8);
        char* st = dsm + s * 16384;
        perm_sts(reinterpret_cast<__half*>(st + soff), a0, a1);
        perm_sts(reinterpret_cast<__half*>(st + 8192 + soff), b0, b1);
    }
    __syncthreads();

    const int gr = lane >> 2;
    const int tq = lane & 3;
    const int KT = K >> 5;

    for (int ktp = 0; ktp < KT; ktp += 2) {
        const bool pf = (ktp + 2 < KT);
        uint4 pa0, pa1, pb0, pb1;
        if (pf) {
            const __half* Ap = Ag + (size_t)(ktp + 2) * 32;
            const __half* Bp = Bg + (size_t)(ktp + 2) * 32;
            pa0 = *reinterpret_cast<const uint4*>(Ap);
            pa1 = *reinterpret_cast<const uint4*>(Ap + 8);
            pb0 = *reinterpret_cast<const uint4*>(Bp);
            pb1 = *reinterpret_cast<const uint4*>(Bp + 8);
        }

        // compute stage ktp & 3
        {
            const __half* st = reinterpret_cast<const __half*>(dsm + (ktp & 3) * 16384);
            #pragma unroll
            for (int kk = 0; kk < 2; ++kk) {
                const __half* ap = st + kk * 2048;
                const __half* bp = ap + 4096;
                uint2 ax[2], ay[2];
                #pragma unroll
                for (int mi = 0; mi < 2; mi++) {
                    const int r = m0 + mi * 16 + gr;
                    ax[mi] = *reinterpret_cast<const uint2*>(ap + r * 16 + tq * 4);
                    ay[mi] = *reinterpret_cast<const uint2*>(ap + (r + 8) * 16 + tq * 4);
                }
                #pragma unroll
                for (int ni = 0; ni < 8; ni++) {
                    const uint2 bv = *reinterpret_cast<const uint2*>(bp + (n0 + ni * 8 + gr) * 16 + tq * 4);
                    #pragma unroll
                    for (int mi = 0; mi < 2; mi++)
                        mma_f16(acc[mi][ni], ax[mi].x, ay[mi].x, ax[mi].y, ay[mi].y, bv.x, bv.y);
                }
            }
        }

        if (pf) {
            char* stn = dsm + ((ktp + 2) & 3) * 16384;
            perm_sts(reinterpret_cast<__half*>(stn + soff), pa0, pa1);
            perm_sts(reinterpret_cast<__half*>(stn + 8192 + soff), pb0, pb1);
            const __half* Ap = Ag + (size_t)(ktp + 3) * 32;
            const __half* Bp = Bg + (size_t)(ktp + 3) * 32;
            pa0 = *reinterpret_cast<const uint4*>(Ap);
            pa1 = *reinterpret_cast<const uint4*>(Ap + 8);
            pb0 = *reinterpret_cast<const uint4*>(Bp);
            pb1 = *reinterpret_cast<const uint4*>(Bp + 8);
        }

        // compute stage (ktp+1) & 3
        {
            const __half* st = reinterpret_cast<const __half*>(dsm + ((ktp + 1) & 3) * 16384);
            #pragma unroll
            for (int kk = 0; kk < 2; ++kk) {
                const __half* ap = st + kk * 2048;
                const __half* bp = ap + 4096;
                uint2 ax[2], ay[2];
                #pragma unroll
                for (int mi = 0; mi < 2; mi++) {
                    const int r = m0 + mi * 16 + gr;
                    ax[mi] = *reinterpret_cast<const uint2*>(ap + r * 16 + tq * 4);
                    ay[mi] = *reinterpret_cast<const uint2*>(ap + (r + 8) * 16 + tq * 4);
                }
                #pragma unroll
                for (int ni = 0; ni < 8; ni++) {
                    const uint2 bv = *reinterpret_cast<const uint2*>(bp + (n0 + ni * 8 + gr) * 16 + tq * 4);
                    #pragma unroll
                    for (int mi = 0; mi < 2; mi++)
                        mma_f16(acc[mi][ni], ax[mi].x, ay[mi].x, ax[mi].y, ay[mi].y, bv.x, bv.y);
                }
            }
        }

        if (pf) {
            char* stn = dsm + ((ktp + 3) & 3) * 16384;
            perm_sts(reinterpret_cast<__half*>(stn + soff), pa0, pa1);
            perm_sts(reinterpret_cast<__half*>(stn + 8192 + soff), pb0, pb1);
            __syncthreads();     // one barrier per 2 k-tiles
        }
    }

    // ---- epilogue ----
    const int gc = tq * 2;
    #pragma unroll
    for (int mi = 0; mi < 2; mi++) {
        #pragma unroll
        for (int ni = 0; ni < 8; ni++) {
            const int r = bm + m0 + mi * 16 + gr;
            const int c = bn + n0 + ni * 8 + gc;
            float2 lo = make_float2(acc[mi][ni][0], acc[mi][ni][1]);
            float2 hi = make_float2(acc[mi][ni][2], acc[mi][ni][3]);
            if (MODE == 0) {
                float2 rlo = *reinterpret_cast<const float2*>(Res + (size_t)r * N + c);
                float2 rhi = *reinterpret_cast<const float2*>(Res + (size_t)(r + 8) * N + c);
                lo.x += rlo.x; lo.y += rlo.y;
                hi.x += rhi.x; hi.y += rhi.y;
                float* C = (float*)Cv;
                *reinterpret_cast<float2*>(C + (size_t)r * N + c)       = lo;
                *reinterpret_cast<float2*>(C + (size_t)(r + 8) * N + c) = hi;
            } else if (MODE == 1) {
                rope_store(lo, r,     c, fcp, qp, kp, vp);
                rope_store(hi, r + 8, c, fcp, qp, kp, vp);
            } else {
                const int j = c >> 1;
                const float a0 = lo.x * lo.y / (1.f + __expf(-lo.x));
                const float a1 = hi.x * hi.y / (1.f + __expf(-hi.x));
                __half* act = (__half*)Cv;
                act[(size_t)r * F_ + j]       = __float2half(a0);
                act[(size_t)(r + 8) * F_ + j] = __float2half(a1);
            }
        }
    }
}

// ============================================================
// Flash attention, fp16 mma, causal, GQA 4:1. fp16 output.
// 128 q-rows x 64 k-cols per block, 256 thr (8 warps x 16 rows).
// Register-staged K/V prefetch (proven R15 form).
// ============================================================
__global__ __launch_bounds__(256) void attn_mma_kernel(
    const __half* __restrict__ qr, const __half* __restrict__ kr,
    const __half* __restrict__ vr, __half* __restrict__ of)
{
    __shared__ __align__(16) __half sQ[4][128][16];
    __shared__ __align__(16) __half sK[4][64][16];
    __shared__ __align__(16) __half sV[64][72];

    const int tid  = threadIdx.x;
    const int lane = tid & 31, warp = tid >> 5;
    const int qt = blockIdx.x, h = blockIdx.y, b = blockIdx.z;
    const int kvh = h >> 2;
    const __half* Q = qr + (((size_t)(b*H_ + h)) * S_ + qt*128) * HD_;
    const __half* K = kr + ((size_t)(b*KH_ + kvh)) * S_ * HD_;
    const __half* V = vr + ((size_t)(b*KH_ + kvh)) * S_ * HD_;

    const int lr0 = tid >> 3,           lseg0 = tid & 7;
    const int lr1 = (tid + 256) >> 3,   lseg1 = (tid + 256) & 7;

    #pragma unroll
    for (int it = 0; it < 4; it++) {
        const int f = tid + it*256;
        const int r = f >> 3, seg = f & 7;
        const int g = seg >> 1, hp = seg & 1;
        uint4 v4 = *reinterpret_cast<const uint4*>(Q + (size_t)r*64 + seg*8);
        uint32_t* p = reinterpret_cast<uint32_t*>(&sQ[g][r][0]);
        p[hp] = v4.x; p[hp+2] = v4.y; p[hp+4] = v4.z; p[hp+6] = v4.w;
    }

    const int gr = lane >> 2;
    const int tq = lane & 3;
    const int qrow = warp * 16;
    const int lm_r = (lane & 7) + ((lane >> 3) & 1) * 8;
    const int lm_c = ((lane >> 4) & 1) * 8;

    float m0 = -1e30f, m1 = -1e30f, l0 = 0.f, l1 = 0.f;
    float oac[8][4];
    #pragma unroll
    for (int i = 0; i < 8; i++)
        oac[i][0] = oac[i][1] = oac[i][2] = oac[i][3] = 0.f;

    const int KTILES = 2*qt + 2;

    uint4 pk0 = *reinterpret_cast<const uint4*>(K + (size_t)lr0*64 + lseg0*8);
    uint4 pv0 = *reinterpret_cast<const uint4*>(V + (size_t)lr0*64 + lseg0*8);
    uint4 pk1 = *reinterpret_cast<const uint4*>(K + (size_t)lr1*64 + lseg1*8);
    uint4 pv1 = *reinterpret_cast<const uint4*>(V + (size_t)lr1*64 + lseg1*8);

    for (int kt = 0; kt < KTILES; ++kt) {
        __syncthreads();
        {
            const int g0 = lseg0 >> 1, hp0 = lseg0 & 1;
            uint32_t* p = reinterpret_cast<uint32_t*>(&sK[g0][lr0][0]);
            p[hp0] = pk0.x; p[hp0+2] = pk0.y; p[hp0+4] = pk0.z; p[hp0+6] = pk0.w;
            *reinterpret_cast<uint4*>(&sV[lr0][lseg0*8]) = pv0;
            const int g1 = lseg1 >> 1, hp1 = lseg1 & 1;
            uint32_t* q = reinterpret_cast<uint32_t*>(&sK[g1][lr1][0]);
            q[hp1] = pk1.x; q[hp1+2] = pk1.y; q[hp1+4] = pk1.z; q[hp1+6] = pk1.w;
            *reinterpret_cast<uint4*>(&sV[lr1][lseg1*8]) = pv1;
        }
        __syncthreads();

        if (kt + 1 < KTILES) {
            const __half* Kn = K + ((size_t)(kt+1)*64)*64;
            const __half* Vn = V + ((size_t)(kt+1)*64)*64;
            pk0 = *reinterpret_cast<const uint4*>(Kn + (size_t)lr0*64 + lseg0*8);
            pv0 = *reinterpret_cast<const uint4*>(Vn + (size_t)lr0*64 + lseg0*8);
            pk1 = *reinterpret_cast<const uint4*>(Kn + (size_t)lr1*64 + lseg1*8);
            pv1 = *reinterpret_cast<const uint4*>(Vn + (size_t)lr1*64 + lseg1*8);
        }

        float sc[8][4];
        #pragma unroll
        for (int i = 0; i < 8; i++)
            sc[i][0] = sc[i][1] = sc[i][2] = sc[i][3] = 0.f;
        #pragma unroll
        for (int kk = 0; kk < 4; kk++) {
            const uint2 alo = *reinterpret_cast<const uint2*>(&sQ[kk][qrow + gr    ][tq*4]);
            const uint2 ahi = *reinterpret_cast<const uint2*>(&sQ[kk][qrow + gr + 8][tq*4]);
            #pragma unroll
            for (int ni = 0; ni < 8; ni++) {
                const uint2 bv = *reinterpret_cast<const uint2*>(&sK[kk][ni*8 + gr][tq*4]);
                mma_f16(sc[ni], alo.x, ahi.x, alo.y, ahi.y, bv.x, bv.y);
            }
        }

        if (kt >= 2*qt) {
            const int r0g = qt*128 + qrow + gr;
            const int r1g = r0g + 8;
            #pragma unroll
            for (int ni = 0; ni < 8; ni++) {
                const int c0 = kt*64 + ni*8 + tq*2, c1 = c0 + 1;
                if (c0 > r0g) sc[ni][0] = -1e30f;
                if (c1 > r0g) sc[ni][1] = -1e30f;
                if (c0 > r1g) sc[ni][2] = -1e30f;
                if (c1 > r1g) sc[ni][3] = -1e30f;
            }
        }

        float mx0 = -1e30f, mx1 = -1e30f;
        #pragma unroll
        for (int ni = 0; ni < 8; ni++) {
            mx0 = fmaxf(mx0, fmaxf(sc[ni][0], sc[ni][1]));
            mx1 = fmaxf(mx1, fmaxf(sc[ni][2], sc[ni][3]));
        }
        mx0 = fmaxf(mx0, __shfl_xor_sync(0xffffffffu, mx0, 1));
        mx0 = fmaxf(mx0, __shfl_xor_sync(0xffffffffu, mx0, 2));
        mx1 = fmaxf(mx1, __shfl_xor_sync(0xffffffffu, mx1, 1));
        mx1 = fmaxf(mx1, __shfl_xor_sync(0xffffffffu, mx1, 2));
        const float nm0 = fmaxf(m0, mx0), nm1 = fmaxf(m1, mx1);
        const float al0 = __expf(m0 - nm0), al1 = __expf(m1 - nm1);
        m0 = nm0; m1 = nm1;

        float s0 = 0.f, s1 = 0.f;
        uint32_t pa[4][4];
        #pragma unroll
        for (int ni = 0; ni < 8; ni++) {
            const float p0 = __expf(sc[ni][0] - nm0);
            const float p1 = __expf(sc[ni][1] - nm0);
            const float p2 = __expf(sc[ni][2] - nm1);
            const float p3 = __expf(sc[ni][3] - nm1);
            s0 += p0 + p1; s1 += p2 + p3;
            const int kk = ni >> 1, w2 = (ni & 1) * 2;
            pa[kk][w2    ] = packh2(p0, p1);
            pa[kk][w2 + 1] = packh2(p2, p3);
        }
        s0 += __shfl_xor_sync(0xffffffffu, s0, 1);
        s0 += __shfl_xor_sync(0xffffffffu, s0, 2);
        s1 += __shfl_xor_sync(0xffffffffu, s1, 1);
        s1 += __shfl_xor_sync(0xffffffffu, s1, 2);
        l0 = l0 * al0 + s0;
        l1 = l1 * al1 + s1;
        #pragma unroll
        for (int ni = 0; ni < 8; ni++) {
            oac[ni][0] *= al0; oac[ni][1] *= al0;
            oac[ni][2] *= al1; oac[ni][3] *= al1;
        }

        #pragma unroll
        for (int kk = 0; kk < 4; kk++) {
            uint32_t bfr[8][2];
            #pragma unroll
            for (int nip = 0; nip < 4; nip++) {
                const uint32_t addr = smem_u32(&sV[16*kk + lm_r][nip*16 + lm_c]);
                asm volatile(
                    "ldmatrix.sync.aligned.m8n8.x4.trans.shared.b16 {%0,%1,%2,%3}, [%4];"
                    : "=r"(bfr[2*nip][0]), "=r"(bfr[2*nip][1]),
                      "=r"(bfr[2*nip+1][0]), "=r"(bfr[2*nip+1][1])
                    : "r"(addr));
            }
            #pragma unroll
            for (int ni = 0; ni < 8; ni++)
                mma_f16(oac[ni], pa[kk][0], pa[kk][1], pa[kk][2], pa[kk][3],
                        bfr[ni][0], bfr[ni][1]);
        }
    }

    const float il0 = 1.0f / l0, il1 = 1.0f / l1;
    const size_t row0 = (size_t)b * S_ + qt*128 + qrow + gr;
    __half* o0 = of + row0 * E_ + h*64;
    __half* o1 = o0 + (size_t)8 * E_;
    #pragma unroll
    for (int ni = 0; ni < 8; ni++) {
        *reinterpret_cast<uint32_t*>(o0 + ni*8 + tq*2) = packh2(oac[ni][0]*il0, oac[ni][1]*il0);
        *reinterpret_cast<uint32_t*>(o1 + ni*8 + tq*2) = packh2(oac[ni][2]*il1, oac[ni][3]*il1);
    }
}

#define GEMM_SMEM (4 * 16384)

// ============================================================
// launch — R15 stream structure; GEMMs now take 64KB dynamic smem.
// ============================================================
extern "C" void kernel_launch(void* const* d_in, const int* in_sizes, int n_in,
                              void* d_out, int out_size)
{
    (void)in_sizes; (void)n_in; (void)out_size;
    const float* x     = (const float*)d_in[0];
    const float* fc    = (const float*)d_in[2];
    const float* w_qkv = (const float*)d_in[3];
    const float* w_o   = (const float*)d_in[4];
    const float* w1    = (const float*)d_in[5];
    const float* w2    = (const float*)d_in[6];
    const float* w3    = (const float*)d_in[7];
    const float* anw   = (const float*)d_in[8];
    const float* fnw   = (const float*)d_in[9];
    float* out = (float*)d_out;

    __half *wqkvh, *woh, *w13h, *w2h;
    __half *h, *qh, *kh, *vh, *o, *g, *act;
    float  *h2;
    cudaGetSymbolAddress((void**)&wqkvh, g_wqkvh);
    cudaGetSymbolAddress((void**)&woh,   g_woh);
    cudaGetSymbolAddress((void**)&w13h,  g_w13h);
    cudaGetSymbolAddress((void**)&w2h,   g_w2h);
    cudaGetSymbolAddress((void**)&h,     g_h);
    cudaGetSymbolAddress((void**)&qh,    g_qh);
    cudaGetSymbolAddress((void**)&kh,    g_kh);
    cudaGetSymbolAddress((void**)&vh,    g_vh);
    cudaGetSymbolAddress((void**)&o,     g_o);
    cudaGetSymbolAddress((void**)&h2,    g_h2);
    cudaGetSymbolAddress((void**)&g,     g_g);
    cudaGetSymbolAddress((void**)&act,   g_act);

    cudaFuncSetAttribute(hgemm16<0>, cudaFuncAttributeMaxDynamicSharedMemorySize, GEMM_SMEM);
    cudaFuncSetAttribute(hgemm16<1>, cudaFuncAttributeMaxDynamicSharedMemorySize, GEMM_SMEM);
    cudaFuncSetAttribute(hgemm16<2>, cudaFuncAttributeMaxDynamicSharedMemorySize, GEMM_SMEM);

    // Side stream + fork/join events (host objects; created per call, bounded leak).
    cudaStream_t s2;
    cudaEvent_t evFork, evQkvW, evJoin;
    cudaStreamCreateWithFlags(&s2, cudaStreamNonBlocking);
    cudaEventCreateWithFlags(&evFork, cudaEventDisableTiming);
    cudaEventCreateWithFlags(&evQkvW, cudaEventDisableTiming);
    cudaEventCreateWithFlags(&evJoin, cudaEventDisableTiming);

    // fork
    cudaEventRecord(evFork, 0);
    cudaStreamWaitEvent(s2, evFork, 0);

    // side stream: qkv weights first (overlaps main-stream rmsnorm), then the rest
    f2h_kernel<<<(QKVN*E_)/2048, 256, 0, s2>>>(w_qkv, wqkvh);
    cudaEventRecord(evQkvW, s2);
    f2h_kernel<<<(E_*E_)/2048, 256, 0, s2>>>(w_o, woh);
    f2h_w13_kernel<<<(F_*E_)/2048, 256, 0, s2>>>(w1, w3, w13h);
    f2h_kernel<<<(E_*F_)/2048, 256, 0, s2>>>(w2, w2h);
    cudaEventRecord(evJoin, s2);

    // main stream
    rmsnorm_kernel<<<M_, 256>>>(x, anw, h);
    cudaStreamWaitEvent(0, evQkvW, 0);
    hgemm16<1><<<dim3(QKVN/128, M_/128), 256, GEMM_SMEM>>>(h, wqkvh, nullptr, nullptr,
                                                           fc, qh, kh, vh, M_, QKVN, E_);
    attn_mma_kernel<<<dim3(S_/128, H_, B_), 256>>>(qh, kh, vh, o);

    // join: remaining GEMMs need the side-stream weights
    cudaStreamWaitEvent(0, evJoin, 0);

    // h2 = x + o @ w_o^T
    hgemm16<0><<<dim3(E_/128, M_/128), 256, GEMM_SMEM>>>(o, woh, x, h2,
                                                         nullptr, nullptr, nullptr, nullptr, M_, E_, E_);
    // ffn rmsnorm
    rmsnorm_kernel<<<M_, 256>>>(h2, fnw, g);
    // w13 GEMM + fused SwiGLU
    hgemm16<2><<<dim3((2*F_)/128, M_/128), 256, GEMM_SMEM>>>(g, w13h, nullptr, act,
                                                             nullptr, nullptr, nullptr, nullptr, M_, 2*F_, E_);
    // out = h2 + act @ w2^T
    hgemm16<0><<<dim3(E_/128, M_/128), 256, GEMM_SMEM>>>(act, w2h, h2, out,
                                                         nullptr, nullptr, nullptr, nullptr, M_, E_, F_);
}